// round 14
// baseline (speedup 1.0000x reference)
#include <cuda_runtime.h>
#include <cuda_bf16.h>
#include <math.h>
#include <stdint.h>

#define Bq 64
#define TSq 300
#define TDq 180
#define Fq 128
#define Hq 512
#define Lq 4
#define Gq 2048   // 4*H

// ---------------- static device scratch (no runtime allocation) ----------------
__device__ float g_xp[(size_t)2 * Bq * TSq * Gq];
__device__ unsigned g_hwork[2][2 * Bq * Hq];          // packed bf16 hi|lo h state
__device__ float g_cwork[2 * Bq * Hq];
__device__ float g_hs[Lq * Bq * 1024];
__device__ float g_cs[Lq * Bq * 1024];
__device__ float g_h0[Lq * Bq * Hq];
__device__ float g_c0[Lq * Bq * Hq];
__device__ unsigned g_barSlots[16 * 32];
// bf16 split operand planes for tensor-core GEMMs
__device__ __nv_bfloat16 g_Ah[(size_t)Bq * TSq * 1024];
__device__ __nv_bfloat16 g_Al[(size_t)Bq * TSq * 1024];
__device__ __nv_bfloat16 g_Wh[(size_t)2 * Gq * 1024];
__device__ __nv_bfloat16 g_Wl[(size_t)2 * Gq * 1024];

// -------- helpers (compute_103-safe) -----
__device__ __forceinline__ uint32_t smem_u32(const void* p) {
    uint32_t a;
    asm("{ .reg .u64 t; cvta.to.shared.u64 t, %1; cvt.u32.u64 %0, t; }" : "=r"(a) : "l"(p));
    return a;
}
#define LDM_X4(r0, r1, r2, r3, addr) \
    asm volatile("ldmatrix.sync.aligned.m8n8.x4.shared.b16 {%0,%1,%2,%3}, [%4];" \
        : "=r"(r0), "=r"(r1), "=r"(r2), "=r"(r3) : "r"(addr))
#define LDM_X2(r0, r1, addr) \
    asm volatile("ldmatrix.sync.aligned.m8n8.x2.shared.b16 {%0,%1}, [%2];" \
        : "=r"(r0), "=r"(r1) : "r"(addr))
#define MMA_BF16(c0, c1, c2, c3, a0, a1, a2, a3, b0, b1) \
    asm volatile("mma.sync.aligned.m16n8k16.row.col.f32.bf16.bf16.f32 " \
        "{%0,%1,%2,%3}, {%4,%5,%6,%7}, {%8,%9}, {%0,%1,%2,%3};" \
        : "+f"(c0), "+f"(c1), "+f"(c2), "+f"(c3) \
        : "r"(a0), "r"(a1), "r"(a2), "r"(a3), "r"(b0), "r"(b1))

// mbarrier + bulk-async
#define MB_INIT(mb, cnt) \
    asm volatile("mbarrier.init.shared.b64 [%0], %1;" :: "r"(mb), "r"(cnt) : "memory")
#define MB_EXPECT(mb, bytes) \
    asm volatile("mbarrier.arrive.expect_tx.shared.b64 _, [%0], %1;" :: "r"(mb), "r"(bytes) : "memory")
#define MB_WAIT(mb, par) do { \
    uint32_t _mb = (mb), _p = (par), _d; \
    asm volatile("{\n\t.reg .pred p;\n\t" \
        "mbarrier.try_wait.parity.acquire.cta.shared::cta.b64 p, [%1], %2;\n\t" \
        "selp.b32 %0, 1, 0, p;\n\t}" : "=r"(_d) : "r"(_mb), "r"(_p) : "memory"); \
    if (!_d) { \
        asm volatile("{\n\t.reg .pred P1;\n\t" \
            "WL_%=:\n\t" \
            "mbarrier.try_wait.parity.acquire.cta.shared::cta.b64 P1, [%0], %1, 0x989680;\n\t" \
            "@P1 bra.uni WD_%=;\n\t" \
            "bra.uni WL_%=;\n\t" \
            "WD_%=:\n\t}" :: "r"(_mb), "r"(_p) : "memory"); \
    } \
} while (0)
#define BULK_G2S(dst, src, nbytes, mb) \
    asm volatile("cp.async.bulk.shared::cta.global.mbarrier::complete_tx::bytes [%0], [%1], %2, [%3];" \
        :: "r"(dst), "l"(src), "r"(nbytes), "r"(mb) : "memory")

__device__ __forceinline__ uint32_t bf2pack(float fhi, float flo) {
    uint32_t r;
    asm("cvt.rn.bf16x2.f32 %0, %1, %2;" : "=r"(r) : "f"(fhi), "f"(flo));
    return r;
}
__device__ __forceinline__ float trunc_hi(float f) {
    return __uint_as_float(__float_as_uint(f) & 0xFFFF0000u);
}
__device__ __forceinline__ unsigned packHL(float f) {
    const float lo = f - trunc_hi(f);
    unsigned lo16;
    asm("{ .reg .b16 t; cvt.rn.bf16.f32 t, %1; cvt.u32.u16 %0, t; }" : "=r"(lo16) : "f"(lo));
    return (__float_as_uint(f) & 0xFFFF0000u) | lo16;
}
__device__ __forceinline__ float unpackHL(unsigned w) {
    return __uint_as_float(w & 0xFFFF0000u) + __uint_as_float(w << 16);
}
__device__ __forceinline__ unsigned prmt(unsigned a, unsigned b, unsigned sel) {
    return __byte_perm(a, b, sel);
}
__device__ __forceinline__ float fast_tanh(float x) {
    float r;
    asm("tanh.approx.f32 %0, %1;" : "=f"(r) : "f"(x));
    return r;
}
__device__ __forceinline__ float fast_sigmoid(float x) {
    return fmaf(0.5f, fast_tanh(0.5f * x), 0.5f);
}

// ---------------------------------------------------------------------------
// grid barrier on a monotonic counter
// ---------------------------------------------------------------------------
__device__ __forceinline__ void gbar(unsigned* slot, unsigned tgt)
{
    __syncthreads();
    if (threadIdx.x == 0) {
        asm volatile("red.release.gpu.global.add.u32 [%0], 1;" :: "l"(slot) : "memory");
        unsigned v;
        while (true) {
            asm volatile("ld.acquire.gpu.global.u32 %0, [%1];" : "=r"(v) : "l"(slot) : "memory");
            if (v >= tgt) break;
            __nanosleep(32);
        }
    }
    __syncthreads();
}

// ---------------------------------------------------------------------------
// fp32 -> bf16 hi/lo split planes, n % 4 == 0
// ---------------------------------------------------------------------------
__global__ void conv_split(const float* __restrict__ in, __nv_bfloat16* __restrict__ hi,
                           __nv_bfloat16* __restrict__ lo, size_t n)
{
    const size_t i = ((size_t)blockIdx.x * 256 + threadIdx.x) * 4;
    if (i >= n) return;
    const float4 v = *(const float4*)(in + i);
    uint2 h, l;
    h.x = prmt(__float_as_uint(v.x), __float_as_uint(v.y), 0x7632);
    h.y = prmt(__float_as_uint(v.z), __float_as_uint(v.w), 0x7632);
    l.x = bf2pack(v.y - trunc_hi(v.y), v.x - trunc_hi(v.x));
    l.y = bf2pack(v.w - trunc_hi(v.w), v.z - trunc_hi(v.z));
    *(uint2*)(hi + i) = h;
    *(uint2*)(lo + i) = l;
}

// ---------------------------------------------------------------------------
// Bulk-async split-bf16 GEMM: C[M,N] = op(A[M,K] @ W[N,K]^T + b)
// D = Ah*Wh + Ah*Wl + Al*Wh.
// Producer: cp.async.bulk, 64B/row, 4 planes (Ah|Al|Wh|Wl), 512 ops/chunk.
// Consumer: round-9 ldmatrix fragments; rows at 80B stride -> conflict-free,
// no swizzle. CTA 128x128, 256 threads (8 warps 2x4), warp 64x32,
// K chunks of 32, 2 stages, 2 CTAs/SM. M%128==0, N%128==0, K%32==0, K>=96.
// ---------------------------------------------------------------------------
#define BB_ROWB   80
#define BB_PLANE  (128 * BB_ROWB)          // 10240
#define BB_STAGE  (4 * BB_PLANE)           // 40960
#define BB_SMEM   (2 * BB_STAGE + 64)

__global__ __launch_bounds__(256, 2)
void mma_xp(const __nv_bfloat16* __restrict__ Ah, const __nv_bfloat16* __restrict__ Al,
            const __nv_bfloat16* __restrict__ Wh, const __nv_bfloat16* __restrict__ Wl,
            const float* __restrict__ bias, float* __restrict__ C,
            int M, int N, int K, size_t wZ, size_t bZ, size_t cZ, int act)
{
    extern __shared__ __align__(128) char smem[];
    const uint32_t sbase  = smem_u32(smem);
    const uint32_t mbBase = sbase + 2 * BB_STAGE;

    Wh   += blockIdx.z * wZ;
    Wl   += blockIdx.z * wZ;
    bias += blockIdx.z * bZ;
    C    += blockIdx.z * cZ;
    const int n0 = blockIdx.x * 128;
    const int m0 = blockIdx.y * 128;

    const int tid  = threadIdx.x;
    const int lane = tid & 31;
    const int warp = tid >> 5;
    const int wm = warp >> 2;          // 0..1
    const int wn = warp & 3;           // 0..3

    // producer mapping: 512 rows-of-plane per chunk, 2 per thread
    const int i0 = tid, i1 = tid + 256;
    const int pl0 = i0 >> 7, r0 = i0 & 127;
    const int pl1 = i1 >> 7, r1 = i1 & 127;
    const __nv_bfloat16* src0 =
        (pl0 == 0) ? Ah + (size_t)(m0 + r0) * K :
                     Al + (size_t)(m0 + r0) * K;
    const __nv_bfloat16* src1 =
        (pl1 == 2) ? Wh + (size_t)(n0 + r1) * K :
                     Wl + (size_t)(n0 + r1) * K;
    const uint32_t dst0 = (uint32_t)(pl0 * BB_PLANE + r0 * BB_ROWB);
    const uint32_t dst1 = (uint32_t)(pl1 * BB_PLANE + r1 * BB_ROWB);

    if (tid < 2) MB_INIT(mbBase + tid * 8, 1);
    __syncthreads();

    float acc[4][4][4];
#pragma unroll
    for (int i = 0; i < 4; i++)
#pragma unroll
        for (int j = 0; j < 4; j++)
#pragma unroll
            for (int q = 0; q < 4; q++) acc[i][j][q] = 0.f;

    // ldmatrix address components (round-9 pattern, stride 80, no swizzle)
    const int arow = wm * 64 + (lane & 15);
    const int agoff = lane >> 4;
    const int brow = wn * 32 + (lane & 7);
    const int bgoff = (lane >> 3) & 1;
    const int bnt   = lane >> 4;

    const int nch = K >> 5;

#define BISSUE(c) do { \
    const uint32_t _sb = sbase + (uint32_t)((c) & 1) * BB_STAGE; \
    const size_t _ko = (size_t)((c) << 5); \
    BULK_G2S(_sb + dst0, src0 + _ko, 64, mbBase + ((c) & 1) * 8); \
    BULK_G2S(_sb + dst1, src1 + _ko, 64, mbBase + ((c) & 1) * 8); \
} while (0)

    // prologue: expect both stages, then issue chunks 0 and 1
    if (tid == 0) { MB_EXPECT(mbBase, 32768); MB_EXPECT(mbBase + 8, 32768); }
    __syncthreads();
    BISSUE(0);
    BISSUE(1);

    for (int c = 0; c < nch; c++) {
        MB_WAIT(mbBase + (c & 1) * 8, (c >> 1) & 1);

        const uint32_t buf = sbase + (uint32_t)(c & 1) * BB_STAGE;
        const uint32_t aH = buf;
        const uint32_t aL = buf + BB_PLANE;
        const uint32_t wH = buf + 2 * BB_PLANE;
        const uint32_t wL = buf + 3 * BB_PLANE;

#pragma unroll
        for (int ks = 0; ks < 2; ks++) {
            uint32_t af[4][4], bh[4][2], bl[4][2];
#pragma unroll
            for (int mt = 0; mt < 4; mt++) {
                const int rA = arow + mt * 16;
                const uint32_t ad = aH + (uint32_t)(rA * BB_ROWB + ((ks * 2 + agoff) << 4));
                LDM_X4(af[mt][0], af[mt][1], af[mt][2], af[mt][3], ad);
            }
#pragma unroll
            for (int p = 0; p < 2; p++) {
                const int rB = brow + (p * 2 + bnt) * 8;
                const uint32_t off = (uint32_t)(rB * BB_ROWB + ((ks * 2 + bgoff) << 4));
                LDM_X4(bh[p * 2][0], bh[p * 2][1], bh[p * 2 + 1][0], bh[p * 2 + 1][1], wH + off);
                LDM_X4(bl[p * 2][0], bl[p * 2][1], bl[p * 2 + 1][0], bl[p * 2 + 1][1], wL + off);
            }
#pragma unroll
            for (int mt = 0; mt < 4; mt++)
#pragma unroll
                for (int nt = 0; nt < 4; nt++)
                    MMA_BF16(acc[mt][nt][0], acc[mt][nt][1], acc[mt][nt][2], acc[mt][nt][3],
                             af[mt][0], af[mt][1], af[mt][2], af[mt][3],
                             bh[nt][0], bh[nt][1]);
#pragma unroll
            for (int mt = 0; mt < 4; mt++)
#pragma unroll
                for (int nt = 0; nt < 4; nt++)
                    MMA_BF16(acc[mt][nt][0], acc[mt][nt][1], acc[mt][nt][2], acc[mt][nt][3],
                             af[mt][0], af[mt][1], af[mt][2], af[mt][3],
                             bl[nt][0], bl[nt][1]);
#pragma unroll
            for (int mt = 0; mt < 4; mt++) {
                const int rA = arow + mt * 16;
                const uint32_t ad = aL + (uint32_t)(rA * BB_ROWB + ((ks * 2 + agoff) << 4));
                LDM_X4(af[mt][0], af[mt][1], af[mt][2], af[mt][3], ad);
            }
#pragma unroll
            for (int mt = 0; mt < 4; mt++)
#pragma unroll
                for (int nt = 0; nt < 4; nt++)
                    MMA_BF16(acc[mt][nt][0], acc[mt][nt][1], acc[mt][nt][2], acc[mt][nt][3],
                             af[mt][0], af[mt][1], af[mt][2], af[mt][3],
                             bh[nt][0], bh[nt][1]);
        }

        __syncthreads();                            // all reads of stage done
        if (c + 2 < nch) {
            if (tid == 0) MB_EXPECT(mbBase + (c & 1) * 8, 32768);
            __syncthreads();                        // expect before any tx
            BISSUE(c + 2);
        }
    }

    const int mE = m0 + wm * 64 + (lane >> 2);
    const int nE = n0 + wn * 32 + (lane & 3) * 2;
#pragma unroll
    for (int mt = 0; mt < 4; mt++) {
#pragma unroll
        for (int nt = 0; nt < 4; nt++) {
            const int m = mE + mt * 16;
            const int n = nE + nt * 8;
            const float b0 = bias[n], b1 = bias[n + 1];
            float v00 = acc[mt][nt][0] + b0, v01 = acc[mt][nt][1] + b1;
            float v10 = acc[mt][nt][2] + b0, v11 = acc[mt][nt][3] + b1;
            if (act) { v00 = tanhf(v00); v01 = tanhf(v01); v10 = tanhf(v10); v11 = tanhf(v11); }
            *(float2*)(C + (size_t)m * N + n)       = make_float2(v00, v01);
            *(float2*)(C + (size_t)(m + 8) * N + n) = make_float2(v10, v11);
        }
    }
}

// ---------------------------------------------------------------------------
// Persistent LSTM layer with tensor-core recurrence (round-11 structure:
// packed h state, y written as separate hi/lo u16 planes, fast activations).
// ---------------------------------------------------------------------------
template<int NBL>
__global__ __launch_bounds__(256)
void lstm_persist(const float* __restrict__ xp, const float* __restrict__ Whh,
                  const float* __restrict__ h0, const float* __restrict__ c0,
                  unsigned* __restrict__ hA, unsigned* __restrict__ hB,
                  float* __restrict__ cSt,
                  __nv_bfloat16* __restrict__ yh, __nv_bfloat16* __restrict__ yl,
                  float* __restrict__ hFin, float* __restrict__ cFin,
                  int T, int revDir1, int yStride, int yDirMult, int slotIdx)
{
    constexpr int U    = NBL / 4;
    constexpr int USH  = (NBL == 32) ? 3 : 2;
    constexpr int WNT  = NBL / 16;
    constexpr int GSs  = NBL + 2;
    constexpr unsigned G = (NBL == 32) ? 64u : 128u;
    constexpr uint32_t S_AH = 0;
    constexpr uint32_t S_AL = 64 * 1024;
    constexpr uint32_t S_BH = 128 * 1024;
    constexpr uint32_t S_BL = S_BH + NBL * 1024;
    constexpr uint32_t S_GS = S_BL + NBL * 1024;

    extern __shared__ __align__(128) char smem[];
    const uint32_t sb = smem_u32(smem);
    float* Gs = (float*)(smem + S_GS);

    const int tid  = threadIdx.x;
    const int lane = tid & 31;
    const int warp = tid >> 5;
    const int mi = warp >> 1;
    const int nh = warp & 1;

    int dir, u0;
    if (NBL == 32) { dir = blockIdx.x >> 6; u0 = (blockIdx.x & 63) * 8; }
    else           { dir = 0;               u0 = blockIdx.x * 4; }

    unsigned* slot = g_barSlots + (size_t)(slotIdx + ((NBL == 32) ? dir : 0)) * 32;
    unsigned barTgt = 0;

    const float* xpd = xp  + (size_t)dir * Bq * T * Gq;
    const float* Wd  = Whh + (size_t)dir * Gq * Hq;
    unsigned* hArr[2] = { hA + dir * Bq * Hq, hB + dir * Bq * Hq };
    float* cD = cSt + dir * Bq * Hq;

    for (int i = tid; i < NBL * 64; i += 256) {
        const int row = i >> 6;
        const int g   = i & 63;
        const int gate = row / U;
        const int uu   = row & (U - 1);
        const int wrow = (gate << 9) + u0 + uu;
        const float4 va = *(const float4*)(Wd + (size_t)wrow * Hq + g * 8);
        const float4 vb = *(const float4*)(Wd + (size_t)wrow * Hq + g * 8 + 4);
        uint4 hi, lo;
        hi.x = prmt(__float_as_uint(va.x), __float_as_uint(va.y), 0x7632);
        hi.y = prmt(__float_as_uint(va.z), __float_as_uint(va.w), 0x7632);
        hi.z = prmt(__float_as_uint(vb.x), __float_as_uint(vb.y), 0x7632);
        hi.w = prmt(__float_as_uint(vb.z), __float_as_uint(vb.w), 0x7632);
        lo.x = bf2pack(va.y - trunc_hi(va.y), va.x - trunc_hi(va.x));
        lo.y = bf2pack(va.w - trunc_hi(va.w), va.z - trunc_hi(va.z));
        lo.z = bf2pack(vb.y - trunc_hi(vb.y), vb.x - trunc_hi(vb.x));
        lo.w = bf2pack(vb.w - trunc_hi(vb.w), vb.z - trunc_hi(vb.z));
        const uint32_t so = (uint32_t)(row * 1024 + ((g ^ (row & 7)) << 4));
        *(uint4*)(smem + S_BH + so) = hi;
        *(uint4*)(smem + S_BL + so) = lo;
    }

    for (int i = tid; i < Bq * U; i += 256) {
        const int b = i >> USH, uu = i & (U - 1), u = u0 + uu;
        hArr[0][b * Hq + u] = h0 ? packHL(h0[b * Hq + u]) : 0u;
        cD        [b * Hq + u] = c0 ? c0[b * Hq + u] : 0.f;
    }
    barTgt += G; gbar(slot, barTgt);

    const int rowA = (lane & 15);
    const int agoff = lane >> 4;
    const int bnt   = lane >> 4;
    const int bgoff = (lane >> 3) & 1;

    int ping = 0;
    for (int t = 0; t < T; t++) {
        const int tt = (dir == 1 && revDir1) ? (T - 1 - t) : t;
        const unsigned* hI = hArr[ping];
        unsigned*       hO = hArr[ping ^ 1];

#pragma unroll
        for (int it = 0; it < 16; it++) {
            const int slotI = tid + it * 256;
            const int row = slotI >> 6, g = slotI & 63;
            const uint4* p = (const uint4*)(hI + (size_t)row * Hq + g * 8);
            const uint4 v0 = __ldcg(p);
            const uint4 v1 = __ldcg(p + 1);
            uint4 hi, lo;
            hi.x = prmt(v0.x, v0.y, 0x7632); hi.y = prmt(v0.z, v0.w, 0x7632);
            hi.z = prmt(v1.x, v1.y, 0x7632); hi.w = prmt(v1.z, v1.w, 0x7632);
            lo.x = prmt(v0.x, v0.y, 0x5410); lo.y = prmt(v0.z, v0.w, 0x5410);
            lo.z = prmt(v1.x, v1.y, 0x5410); lo.w = prmt(v1.z, v1.w, 0x5410);
            const uint32_t so = (uint32_t)(row * 1024 + ((g ^ (row & 7)) << 4));
            *(uint4*)(smem + S_AH + so) = hi;
            *(uint4*)(smem + S_AL + so) = lo;
        }
        __syncthreads();

        float acc[WNT][4];
#pragma unroll
        for (int nt = 0; nt < WNT; nt++)
#pragma unroll
            for (int q = 0; q < 4; q++) acc[nt][q] = 0.f;

#pragma unroll 4
        for (int ks = 0; ks < 32; ks++) {
            const int rA = mi * 16 + rowA;
            const uint32_t aoff = (uint32_t)(rA * 1024 + (((ks * 2 + agoff) ^ (rA & 7)) << 4));
            uint32_t ah[4], al[4], bh[2 * WNT], bl[2 * WNT];
            LDM_X4(ah[0], ah[1], ah[2], ah[3], sb + S_AH + aoff);
            LDM_X4(al[0], al[1], al[2], al[3], sb + S_AL + aoff);
            if (WNT == 2) {
                const int rB = nh * 16 + bnt * 8 + (lane & 7);
                const uint32_t boff = (uint32_t)(rB * 1024 + (((ks * 2 + bgoff) ^ (rB & 7)) << 4));
                LDM_X4(bh[0], bh[1], bh[2], bh[3], sb + S_BH + boff);
                LDM_X4(bl[0], bl[1], bl[2], bl[3], sb + S_BL + boff);
            } else {
                const int rB = nh * 8 + (lane & 7);
                const uint32_t boff = (uint32_t)(rB * 1024 + (((ks * 2 + bgoff) ^ (rB & 7)) << 4));
                LDM_X2(bh[0], bh[1], sb + S_BH + boff);
                LDM_X2(bl[0], bl[1], sb + S_BL + boff);
            }
#pragma unroll
            for (int nt = 0; nt < WNT; nt++)
                MMA_BF16(acc[nt][0], acc[nt][1], acc[nt][2], acc[nt][3],
                         ah[0], ah[1], ah[2], ah[3], bh[nt * 2], bh[nt * 2 + 1]);
#pragma unroll
            for (int nt = 0; nt < WNT; nt++)
                MMA_BF16(acc[nt][0], acc[nt][1], acc[nt][2], acc[nt][3],
                         ah[0], ah[1], ah[2], ah[3], bl[nt * 2], bl[nt * 2 + 1]);
#pragma unroll
            for (int nt = 0; nt < WNT; nt++)
                MMA_BF16(acc[nt][0], acc[nt][1], acc[nt][2], acc[nt][3],
                         al[0], al[1], al[2], al[3], bh[nt * 2], bh[nt * 2 + 1]);
        }

        {
            const int gr  = lane >> 2;
            const int gcq = (lane & 3) * 2;
            const int m = mi * 16 + gr;
#pragma unroll
            for (int nt = 0; nt < WNT; nt++) {
                const int gc = nh * (WNT * 8) + nt * 8 + gcq;
                *(float2*)&Gs[m * GSs + gc]       = make_float2(acc[nt][0], acc[nt][1]);
                *(float2*)&Gs[(m + 8) * GSs + gc] = make_float2(acc[nt][2], acc[nt][3]);
            }
        }
        __syncthreads();

#pragma unroll
        for (int i = tid; i < Bq * U; i += 256) {
            const int b = i >> USH, uu = i & (U - 1);
            const int u = u0 + uu;
            const size_t xb = ((size_t)b * T + tt) * Gq + u;
            const float iv = Gs[b * GSs + 0 * U + uu] + xpd[xb];
            const float fv = Gs[b * GSs + 1 * U + uu] + xpd[xb + 512];
            const float gv = Gs[b * GSs + 2 * U + uu] + xpd[xb + 1024];
            const float ov = Gs[b * GSs + 3 * U + uu] + xpd[xb + 1536];
            const float cOld = cD[b * Hq + u];
            const float si = fast_sigmoid(iv);
            const float sf = fast_sigmoid(fv);
            const float so = fast_sigmoid(ov);
            const float cN = sf * cOld + si * fast_tanh(gv);
            const float hN = so * fast_tanh(cN);
            const unsigned w = packHL(hN);
            cD[b * Hq + u] = cN;
            hO[b * Hq + u] = w;
            if (yh) {
                const size_t yi = ((size_t)b * T + tt) * yStride + dir * yDirMult + u;
                ((unsigned short*)yh)[yi] = (unsigned short)(w >> 16);
                ((unsigned short*)yl)[yi] = (unsigned short)(w & 0xFFFFu);
            }
        }

        if (t + 1 < T) { barTgt += G; gbar(slot, barTgt); }
        ping ^= 1;
    }

    if (hFin) {
        for (int i = tid; i < Bq * U; i += 256) {
            const int b = i >> USH, uu = i & (U - 1), u = u0 + uu;
            hFin[b * 1024 + dir * 512 + u] = unpackHL(hArr[ping][b * Hq + u]);
            cFin[b * 1024 + dir * 512 + u] = cD[b * Hq + u];
        }
    }
}

#define SMEM_ENC (128 * 1024 + 2 * 32 * 1024 + 64 * 34 * 4)
#define SMEM_DEC (128 * 1024 + 2 * 16 * 1024 + 64 * 18 * 4)

// decoder input: concat(tgt_in, sc_emb[scenario[b]]) -> bf16 hi/lo planes
__global__ void build_dcat(const float* __restrict__ tgt, const float* __restrict__ scEmb,
                           const int* __restrict__ scen,
                           __nv_bfloat16* __restrict__ oh, __nv_bfloat16* __restrict__ ol)
{
    const size_t i = (size_t)blockIdx.x * 256 + threadIdx.x;
    if (i >= (size_t)Bq * TDq * 640) return;
    const int r = (int)(i / 640);
    const int j = (int)(i - (size_t)r * 640);
    float v;
    if (j < 128) v = tgt[(size_t)r * 128 + j];
    else         v = scEmb[scen[r / TDq] * 512 + (j - 128)];
    const unsigned w = packHL(v);
    ((unsigned short*)oh)[i] = (unsigned short)(w >> 16);
    ((unsigned short*)ol)[i] = (unsigned short)(w & 0xFFFFu);
}

// ---------------------------------------------------------------------------
extern "C" void kernel_launch(void* const* d_in, const int* in_sizes, int n_in,
                              void* d_out, int out_size)
{
    (void)in_sizes; (void)n_in; (void)out_size;
    const float* src   = (const float*)d_in[0];
    const float* tgt   = (const float*)d_in[1];
    const int*   scen  = (const int*)  d_in[2];
    const float* eWih0 = (const float*)d_in[3];
    const float* eWhh0 = (const float*)d_in[4];
    const float* eB0   = (const float*)d_in[5];
    const float* eWih  = (const float*)d_in[6];
    const float* eWhh  = (const float*)d_in[7];
    const float* eB    = (const float*)d_in[8];
    const float* hbW   = (const float*)d_in[9];
    const float* hbB   = (const float*)d_in[10];
    const float* cbW   = (const float*)d_in[11];
    const float* cbB   = (const float*)d_in[12];
    const float* scEmb = (const float*)d_in[13];
    const float* dWih0 = (const float*)d_in[14];
    const float* dWhh0 = (const float*)d_in[15];
    const float* dB0   = (const float*)d_in[16];
    const float* dWih  = (const float*)d_in[17];
    const float* dWhh  = (const float*)d_in[18];
    const float* dB    = (const float*)d_in[19];
    const float* outW  = (const float*)d_in[20];
    const float* outB  = (const float*)d_in[21];
    float* out = (float*)d_out;

    float *xp, *cst, *hsP, *csP, *h0P, *c0P;
    unsigned *hwork, *barP;
    __nv_bfloat16 *Ah, *Al, *Wh, *Wl;
    cudaGetSymbolAddress((void**)&xp,    g_xp);
    cudaGetSymbolAddress((void**)&hwork, g_hwork);
    cudaGetSymbolAddress((void**)&cst,   g_cwork);
    cudaGetSymbolAddress((void**)&hsP,   g_hs);
    cudaGetSymbolAddress((void**)&csP,   g_cs);
    cudaGetSymbolAddress((void**)&h0P,   g_h0);
    cudaGetSymbolAddress((void**)&c0P,   g_c0);
    cudaGetSymbolAddress((void**)&barP,  g_barSlots);
    cudaGetSymbolAddress((void**)&Ah,    g_Ah);
    cudaGetSymbolAddress((void**)&Al,    g_Al);
    cudaGetSymbolAddress((void**)&Wh,    g_Wh);
    cudaGetSymbolAddress((void**)&Wl,    g_Wl);
    unsigned* hA = hwork;
    unsigned* hB = hwork + 2 * Bq * Hq;

    cudaFuncSetAttribute(lstm_persist<32>, cudaFuncAttributeMaxDynamicSharedMemorySize, SMEM_ENC);
    cudaFuncSetAttribute(lstm_persist<16>, cudaFuncAttributeMaxDynamicSharedMemorySize, SMEM_DEC);
    cudaFuncSetAttribute(mma_xp, cudaFuncAttributeMaxDynamicSharedMemorySize, BB_SMEM);

    const int ME = Bq * TSq;   // 19200
    const int MD = Bq * TDq;   // 11520

    // reset barrier counters
    cudaMemsetAsync(barP, 0, 16 * 32 * sizeof(unsigned), 0);

    // ======================= encoder =======================
    conv_split<<<(int)(((size_t)ME * Fq / 4 + 255) / 256), 256>>>(src, Ah, Al, (size_t)ME * Fq);

    int inDim = Fq;
    for (int l = 0; l < Lq; l++) {
        const float* Wih = l ? eWih + (size_t)(l - 1) * 2 * Gq * 1024 : eWih0;
        const float* bih = l ? eB   + (size_t)(l - 1) * 2 * Gq        : eB0;

        const size_t nW = (size_t)2 * Gq * inDim;
        conv_split<<<(int)((nW / 4 + 255) / 256), 256>>>(Wih, Wh, Wl, nW);
        mma_xp<<<dim3(Gq / 128, ME / 128, 2), 256, BB_SMEM>>>(
            Ah, Al, Wh, Wl, bih, xp, ME, Gq, inDim,
            (size_t)Gq * inDim, (size_t)Gq, (size_t)ME * Gq, 0);

        const float* Whh = l ? eWhh + (size_t)(l - 1) * 2 * Gq * Hq : eWhh0;
        const int lastEnc = (l == Lq - 1);
        lstm_persist<32><<<128, 256, SMEM_ENC>>>(
            xp, Whh, nullptr, nullptr, hA, hB, cst,
            lastEnc ? nullptr : Ah, lastEnc ? nullptr : Al,
            hsP + (size_t)l * Bq * 1024, csP + (size_t)l * Bq * 1024,
            TSq, 1, 1024, 512, 2 * l);

        inDim = 1024;
    }

    // ======================= bridges (tanh, tensor cores) =======================
    conv_split<<<(int)(((size_t)Lq * Bq * 1024 / 4 + 255) / 256), 256>>>(hsP, Ah, Al, (size_t)Lq * Bq * 1024);
    conv_split<<<(int)(((size_t)Hq * 1024 / 4 + 255) / 256), 256>>>(hbW, Wh, Wl, (size_t)Hq * 1024);
    mma_xp<<<dim3(Hq / 128, (Lq * Bq) / 128, 1), 256, BB_SMEM>>>(
        Ah, Al, Wh, Wl, hbB, h0P, Lq * Bq, Hq, 1024, 0, 0, 0, 1);
    conv_split<<<(int)(((size_t)Lq * Bq * 1024 / 4 + 255) / 256), 256>>>(csP, Ah, Al, (size_t)Lq * Bq * 1024);
    conv_split<<<(int)(((size_t)Hq * 1024 / 4 + 255) / 256), 256>>>(cbW, Wh, Wl, (size_t)Hq * 1024);
    mma_xp<<<dim3(Hq / 128, (Lq * Bq) / 128, 1), 256, BB_SMEM>>>(
        Ah, Al, Wh, Wl, cbB, c0P, Lq * Bq, Hq, 1024, 0, 0, 0, 1);

    // ======================= decoder =======================
    build_dcat<<<(int)(((size_t)Bq * TDq * 640 + 255) / 256), 256>>>(tgt, scEmb, scen, Ah, Al);

    inDim = Fq + Hq;   // 640
    for (int l = 0; l < Lq; l++) {
        const float* Wih = l ? dWih + (size_t)(l - 1) * Gq * Hq : dWih0;
        const float* bih = l ? dB   + (size_t)(l - 1) * Gq      : dB0;

        const size_t nW = (size_t)Gq * inDim;
        conv_split<<<(int)((nW / 4 + 255) / 256), 256>>>(Wih, Wh, Wl, nW);
        mma_xp<<<dim3(Gq / 128, MD / 128, 1), 256, BB_SMEM>>>(
            Ah, Al, Wh, Wl, bih, xp, MD, Gq, inDim, 0, 0, 0, 0);

        const float* Whh = l ? dWhh + (size_t)(l - 1) * Gq * Hq : dWhh0;
        lstm_persist<16><<<128, 256, SMEM_DEC>>>(
            xp, Whh, h0P + (size_t)l * Bq * Hq, c0P + (size_t)l * Bq * Hq,
            hA, hB, cst, Ah, Al, nullptr, nullptr,
            TDq, 0, 512, 0, 8 + l);

        inDim = Hq;
    }

    // output projection straight into d_out
    conv_split<<<(int)(((size_t)Fq * Hq / 4 + 255) / 256), 256>>>(outW, Wh, Wl, (size_t)Fq * Hq);
    mma_xp<<<dim3(Fq / 128, MD / 128, 1), 256, BB_SMEM>>>(
        Ah, Al, Wh, Wl, outB, out, MD, Fq, Hq, 0, 0, 0, 0);
}

// round 15
// speedup vs baseline: 1.1167x; 1.1167x over previous
#include <cuda_runtime.h>
#include <cuda_bf16.h>
#include <math.h>
#include <stdint.h>

#define Bq 64
#define TSq 300
#define TDq 180
#define Fq 128
#define Hq 512
#define Lq 4
#define Gq 2048   // 4*H
#define TILE_E 5120          // 128 rows x 40 u16 per (tile, kChunk)

// ---------------- static device scratch (no runtime allocation) ----------------
__device__ float g_xp[(size_t)2 * Bq * TSq * Gq];
__device__ unsigned g_hwork[2][2 * Bq * Hq];          // packed bf16 hi|lo h state
__device__ float g_cwork[2 * Bq * Hq];
__device__ float g_hs[Lq * Bq * 1024];
__device__ float g_cs[Lq * Bq * 1024];
__device__ float g_h0[Lq * Bq * Hq];
__device__ float g_c0[Lq * Bq * Hq];
__device__ unsigned g_barSlots[16 * 32];
// tiled-padded bf16 operand planes: [tile128][kc32][128][40]
__device__ unsigned short g_Ah[(size_t)150 * 32 * TILE_E];
__device__ unsigned short g_Al[(size_t)150 * 32 * TILE_E];
__device__ unsigned short g_Wh[(size_t)2 * 16 * 32 * TILE_E];
__device__ unsigned short g_Wl[(size_t)2 * 16 * 32 * TILE_E];

// -------- helpers (compute_103-safe) -----
__device__ __forceinline__ uint32_t smem_u32(const void* p) {
    uint32_t a;
    asm("{ .reg .u64 t; cvta.to.shared.u64 t, %1; cvt.u32.u64 %0, t; }" : "=r"(a) : "l"(p));
    return a;
}
#define LDM_X4(r0, r1, r2, r3, addr) \
    asm volatile("ldmatrix.sync.aligned.m8n8.x4.shared.b16 {%0,%1,%2,%3}, [%4];" \
        : "=r"(r0), "=r"(r1), "=r"(r2), "=r"(r3) : "r"(addr))
#define LDM_X2(r0, r1, addr) \
    asm volatile("ldmatrix.sync.aligned.m8n8.x2.shared.b16 {%0,%1}, [%2];" \
        : "=r"(r0), "=r"(r1) : "r"(addr))
#define MMA_BF16(c0, c1, c2, c3, a0, a1, a2, a3, b0, b1) \
    asm volatile("mma.sync.aligned.m16n8k16.row.col.f32.bf16.bf16.f32 " \
        "{%0,%1,%2,%3}, {%4,%5,%6,%7}, {%8,%9}, {%0,%1,%2,%3};" \
        : "+f"(c0), "+f"(c1), "+f"(c2), "+f"(c3) \
        : "r"(a0), "r"(a1), "r"(a2), "r"(a3), "r"(b0), "r"(b1))

// mbarrier + bulk-async
#define MB_INIT(mb, cnt) \
    asm volatile("mbarrier.init.shared.b64 [%0], %1;" :: "r"(mb), "r"(cnt) : "memory")
#define MB_EXPECT(mb, bytes) \
    asm volatile("mbarrier.arrive.expect_tx.shared.b64 _, [%0], %1;" :: "r"(mb), "r"(bytes) : "memory")
#define MB_WAIT(mb, par) do { \
    uint32_t _mb = (mb), _p = (par), _d; \
    asm volatile("{\n\t.reg .pred p;\n\t" \
        "mbarrier.try_wait.parity.acquire.cta.shared::cta.b64 p, [%1], %2;\n\t" \
        "selp.b32 %0, 1, 0, p;\n\t}" : "=r"(_d) : "r"(_mb), "r"(_p) : "memory"); \
    if (!_d) { \
        asm volatile("{\n\t.reg .pred P1;\n\t" \
            "WL_%=:\n\t" \
            "mbarrier.try_wait.parity.acquire.cta.shared::cta.b64 P1, [%0], %1, 0x989680;\n\t" \
            "@P1 bra.uni WD_%=;\n\t" \
            "bra.uni WL_%=;\n\t" \
            "WD_%=:\n\t}" :: "r"(_mb), "r"(_p) : "memory"); \
    } \
} while (0)
#define BULK_G2S(dst, src, nbytes, mb) \
    asm volatile("cp.async.bulk.shared::cta.global.mbarrier::complete_tx::bytes [%0], [%1], %2, [%3];" \
        :: "r"(dst), "l"(src), "r"(nbytes), "r"(mb) : "memory")

__device__ __forceinline__ uint32_t bf2pack(float fhi, float flo) {
    uint32_t r;
    asm("cvt.rn.bf16x2.f32 %0, %1, %2;" : "=r"(r) : "f"(fhi), "f"(flo));
    return r;
}
__device__ __forceinline__ float trunc_hi(float f) {
    return __uint_as_float(__float_as_uint(f) & 0xFFFF0000u);
}
__device__ __forceinline__ unsigned packHL(float f) {
    const float lo = f - trunc_hi(f);
    unsigned lo16;
    asm("{ .reg .b16 t; cvt.rn.bf16.f32 t, %1; cvt.u32.u16 %0, t; }" : "=r"(lo16) : "f"(lo));
    return (__float_as_uint(f) & 0xFFFF0000u) | lo16;
}
__device__ __forceinline__ float unpackHL(unsigned w) {
    return __uint_as_float(w & 0xFFFF0000u) + __uint_as_float(w << 16);
}
__device__ __forceinline__ unsigned prmt(unsigned a, unsigned b, unsigned sel) {
    return __byte_perm(a, b, sel);
}
__device__ __forceinline__ float fast_tanh(float x) {
    float r;
    asm("tanh.approx.f32 %0, %1;" : "=f"(r) : "f"(x));
    return r;
}
__device__ __forceinline__ float fast_sigmoid(float x) {
    return fmaf(0.5f, fast_tanh(0.5f * x), 0.5f);
}
// tiled index: plane[(m>>7)*KC + (k>>5)][m&127][k&31], KC = K/32
__device__ __forceinline__ size_t tidx(size_t m, int k, int KC) {
    return ((m >> 7) * (size_t)KC + (size_t)(k >> 5)) * TILE_E
         + (m & 127) * 40 + (k & 31);
}

// ---------------------------------------------------------------------------
// grid barrier on a monotonic counter
// ---------------------------------------------------------------------------
__device__ __forceinline__ void gbar(unsigned* slot, unsigned tgt)
{
    __syncthreads();
    if (threadIdx.x == 0) {
        asm volatile("red.release.gpu.global.add.u32 [%0], 1;" :: "l"(slot) : "memory");
        unsigned v;
        while (true) {
            asm volatile("ld.acquire.gpu.global.u32 %0, [%1];" : "=r"(v) : "l"(slot) : "memory");
            if (v >= tgt) break;
            __nanosleep(32);
        }
    }
    __syncthreads();
}

// ---------------------------------------------------------------------------
// fp32 row-major [M x K] -> tiled-padded bf16 hi/lo planes. M%128==0, K%32==0.
// ---------------------------------------------------------------------------
__global__ void conv_tiled(const float* __restrict__ in,
                           unsigned short* __restrict__ hi, unsigned short* __restrict__ lo,
                           int M, int K)
{
    const size_t i = ((size_t)blockIdx.x * 256 + threadIdx.x) * 4;
    if (i >= (size_t)M * K) return;
    const size_t m = i / (size_t)K;
    const int k = (int)(i - m * (size_t)K);
    const float4 v = *(const float4*)(in + i);
    uint2 h, l;
    h.x = prmt(__float_as_uint(v.x), __float_as_uint(v.y), 0x7632);
    h.y = prmt(__float_as_uint(v.z), __float_as_uint(v.w), 0x7632);
    l.x = bf2pack(v.y - trunc_hi(v.y), v.x - trunc_hi(v.x));
    l.y = bf2pack(v.w - trunc_hi(v.w), v.z - trunc_hi(v.z));
    const size_t o = tidx(m, k, K >> 5);
    *(uint2*)(hi + o) = h;
    *(uint2*)(lo + o) = l;
}

// ---------------------------------------------------------------------------
// Tiled bulk-async split-bf16 GEMM: C[M,N] = op(A @ W^T + b)
// D = Ah*Wh + Ah*Wl + Al*Wh. Operands in tiled-padded planes -> 4 bulk ops
// (10240B each) per K-chunk per CTA. Consumer: ldmatrix @ 80B stride
// (conflict-free, no swizzle). CTA 128x128, 256 thr, 2 stages, 2 CTAs/SM.
// M%128==0, N%128==0, K%32==0, K>=64.
// ---------------------------------------------------------------------------
#define TB_PLANE  10240
#define TB_STAGE  (4 * TB_PLANE)           // 40960
#define TB_SMEM   (2 * TB_STAGE + 64)

__global__ __launch_bounds__(256, 2)
void mma_xp(const unsigned short* __restrict__ Ah, const unsigned short* __restrict__ Al,
            const unsigned short* __restrict__ Wh, const unsigned short* __restrict__ Wl,
            const float* __restrict__ bias, float* __restrict__ C,
            int M, int N, int K, size_t wZt, size_t bZ, size_t cZ, int act)
{
    extern __shared__ __align__(128) char smem[];
    const uint32_t sbase  = smem_u32(smem);
    const uint32_t mbBase = sbase + 2 * TB_STAGE;

    Wh   += blockIdx.z * wZt;
    Wl   += blockIdx.z * wZt;
    bias += blockIdx.z * bZ;
    C    += blockIdx.z * cZ;
    const int n0 = blockIdx.x * 128;
    const int m0 = blockIdx.y * 128;
    const int KC = K >> 5;

    const int tid  = threadIdx.x;
    const int lane = tid & 31;
    const int warp = tid >> 5;
    const int wm = warp >> 2;          // 0..1
    const int wn = warp & 3;           // 0..3

    const unsigned short* aTh = Ah + (size_t)blockIdx.y * KC * TILE_E;
    const unsigned short* aTl = Al + (size_t)blockIdx.y * KC * TILE_E;
    const unsigned short* wTh = Wh + (size_t)blockIdx.x * KC * TILE_E;
    const unsigned short* wTl = Wl + (size_t)blockIdx.x * KC * TILE_E;

    if (tid < 2) MB_INIT(mbBase + tid * 8, 1);
    __syncthreads();

    float acc[4][4][4];
#pragma unroll
    for (int i = 0; i < 4; i++)
#pragma unroll
        for (int j = 0; j < 4; j++)
#pragma unroll
            for (int q = 0; q < 4; q++) acc[i][j][q] = 0.f;

    // ldmatrix address components (80B stride, no swizzle)
    const int arow = wm * 64 + (lane & 15);
    const int agoff = lane >> 4;
    const int brow = wn * 32 + (lane & 7);
    const int bgoff = (lane >> 3) & 1;
    const int bnt   = lane >> 4;

    const int nch = KC;

#define TISSUE(c) do { \
    const uint32_t _sb = sbase + (uint32_t)((c) & 1) * TB_STAGE; \
    const uint32_t _mb = mbBase + ((c) & 1) * 8; \
    const size_t _o = (size_t)(c) * TILE_E; \
    MB_EXPECT(_mb, 40960); \
    BULK_G2S(_sb,                aTh + _o, TB_PLANE, _mb); \
    BULK_G2S(_sb + TB_PLANE,     aTl + _o, TB_PLANE, _mb); \
    BULK_G2S(_sb + 2 * TB_PLANE, wTh + _o, TB_PLANE, _mb); \
    BULK_G2S(_sb + 3 * TB_PLANE, wTl + _o, TB_PLANE, _mb); \
} while (0)

    if (tid == 0) { TISSUE(0); TISSUE(1); }

    for (int c = 0; c < nch; c++) {
        MB_WAIT(mbBase + (c & 1) * 8, (c >> 1) & 1);

        const uint32_t buf = sbase + (uint32_t)(c & 1) * TB_STAGE;
        const uint32_t aH = buf;
        const uint32_t aL = buf + TB_PLANE;
        const uint32_t wH = buf + 2 * TB_PLANE;
        const uint32_t wL = buf + 3 * TB_PLANE;

#pragma unroll
        for (int ks = 0; ks < 2; ks++) {
            uint32_t af[4][4], bh[4][2], bl[4][2];
#pragma unroll
            for (int mt = 0; mt < 4; mt++) {
                const int rA = arow + mt * 16;
                const uint32_t ad = aH + (uint32_t)(rA * 80 + ((ks * 2 + agoff) << 4));
                LDM_X4(af[mt][0], af[mt][1], af[mt][2], af[mt][3], ad);
            }
#pragma unroll
            for (int p = 0; p < 2; p++) {
                const int rB = brow + (p * 2 + bnt) * 8;
                const uint32_t off = (uint32_t)(rB * 80 + ((ks * 2 + bgoff) << 4));
                LDM_X4(bh[p * 2][0], bh[p * 2][1], bh[p * 2 + 1][0], bh[p * 2 + 1][1], wH + off);
                LDM_X4(bl[p * 2][0], bl[p * 2][1], bl[p * 2 + 1][0], bl[p * 2 + 1][1], wL + off);
            }
#pragma unroll
            for (int mt = 0; mt < 4; mt++)
#pragma unroll
                for (int nt = 0; nt < 4; nt++)
                    MMA_BF16(acc[mt][nt][0], acc[mt][nt][1], acc[mt][nt][2], acc[mt][nt][3],
                             af[mt][0], af[mt][1], af[mt][2], af[mt][3],
                             bh[nt][0], bh[nt][1]);
#pragma unroll
            for (int mt = 0; mt < 4; mt++)
#pragma unroll
                for (int nt = 0; nt < 4; nt++)
                    MMA_BF16(acc[mt][nt][0], acc[mt][nt][1], acc[mt][nt][2], acc[mt][nt][3],
                             af[mt][0], af[mt][1], af[mt][2], af[mt][3],
                             bl[nt][0], bl[nt][1]);
#pragma unroll
            for (int mt = 0; mt < 4; mt++) {
                const int rA = arow + mt * 16;
                const uint32_t ad = aL + (uint32_t)(rA * 80 + ((ks * 2 + agoff) << 4));
                LDM_X4(af[mt][0], af[mt][1], af[mt][2], af[mt][3], ad);
            }
#pragma unroll
            for (int mt = 0; mt < 4; mt++)
#pragma unroll
                for (int nt = 0; nt < 4; nt++)
                    MMA_BF16(acc[mt][nt][0], acc[mt][nt][1], acc[mt][nt][2], acc[mt][nt][3],
                             af[mt][0], af[mt][1], af[mt][2], af[mt][3],
                             bh[nt][0], bh[nt][1]);
        }

        __syncthreads();                            // stage reads done
        if (tid == 0 && c + 2 < nch) TISSUE(c + 2); // refill
    }

    const int mE = m0 + wm * 64 + (lane >> 2);
    const int nE = n0 + wn * 32 + (lane & 3) * 2;
#pragma unroll
    for (int mt = 0; mt < 4; mt++) {
#pragma unroll
        for (int nt = 0; nt < 4; nt++) {
            const int m = mE + mt * 16;
            const int n = nE + nt * 8;
            const float b0 = bias[n], b1 = bias[n + 1];
            float v00 = acc[mt][nt][0] + b0, v01 = acc[mt][nt][1] + b1;
            float v10 = acc[mt][nt][2] + b0, v11 = acc[mt][nt][3] + b1;
            if (act) { v00 = tanhf(v00); v01 = tanhf(v01); v10 = tanhf(v10); v11 = tanhf(v11); }
            *(float2*)(C + (size_t)m * N + n)       = make_float2(v00, v01);
            *(float2*)(C + (size_t)(m + 8) * N + n) = make_float2(v10, v11);
        }
    }
}

// ---------------------------------------------------------------------------
// Persistent LSTM layer (round-14 structure; y written into TILED planes).
// ---------------------------------------------------------------------------
template<int NBL>
__global__ __launch_bounds__(256)
void lstm_persist(const float* __restrict__ xp, const float* __restrict__ Whh,
                  const float* __restrict__ h0, const float* __restrict__ c0,
                  unsigned* __restrict__ hA, unsigned* __restrict__ hB,
                  float* __restrict__ cSt,
                  unsigned short* __restrict__ yh, unsigned short* __restrict__ yl,
                  float* __restrict__ hFin, float* __restrict__ cFin,
                  int T, int revDir1, int yStride, int yDirMult, int slotIdx)
{
    constexpr int U    = NBL / 4;
    constexpr int USH  = (NBL == 32) ? 3 : 2;
    constexpr int WNT  = NBL / 16;
    constexpr int GSs  = NBL + 2;
    constexpr unsigned G = (NBL == 32) ? 64u : 128u;
    constexpr uint32_t S_AH = 0;
    constexpr uint32_t S_AL = 64 * 1024;
    constexpr uint32_t S_BH = 128 * 1024;
    constexpr uint32_t S_BL = S_BH + NBL * 1024;
    constexpr uint32_t S_GS = S_BL + NBL * 1024;

    extern __shared__ __align__(128) char smem[];
    const uint32_t sb = smem_u32(smem);
    float* Gs = (float*)(smem + S_GS);

    const int tid  = threadIdx.x;
    const int lane = tid & 31;
    const int warp = tid >> 5;
    const int mi = warp >> 1;
    const int nh = warp & 1;

    int dir, u0;
    if (NBL == 32) { dir = blockIdx.x >> 6; u0 = (blockIdx.x & 63) * 8; }
    else           { dir = 0;               u0 = blockIdx.x * 4; }

    unsigned* slot = g_barSlots + (size_t)(slotIdx + ((NBL == 32) ? dir : 0)) * 32;
    unsigned barTgt = 0;

    const float* xpd = xp  + (size_t)dir * Bq * T * Gq;
    const float* Wd  = Whh + (size_t)dir * Gq * Hq;
    unsigned* hArr[2] = { hA + dir * Bq * Hq, hB + dir * Bq * Hq };
    float* cD = cSt + dir * Bq * Hq;
    const int yKC = yStride >> 5;

    for (int i = tid; i < NBL * 64; i += 256) {
        const int row = i >> 6;
        const int g   = i & 63;
        const int gate = row / U;
        const int uu   = row & (U - 1);
        const int wrow = (gate << 9) + u0 + uu;
        const float4 va = *(const float4*)(Wd + (size_t)wrow * Hq + g * 8);
        const float4 vb = *(const float4*)(Wd + (size_t)wrow * Hq + g * 8 + 4);
        uint4 hi, lo;
        hi.x = prmt(__float_as_uint(va.x), __float_as_uint(va.y), 0x7632);
        hi.y = prmt(__float_as_uint(va.z), __float_as_uint(va.w), 0x7632);
        hi.z = prmt(__float_as_uint(vb.x), __float_as_uint(vb.y), 0x7632);
        hi.w = prmt(__float_as_uint(vb.z), __float_as_uint(vb.w), 0x7632);
        lo.x = bf2pack(va.y - trunc_hi(va.y), va.x - trunc_hi(va.x));
        lo.y = bf2pack(va.w - trunc_hi(va.w), va.z - trunc_hi(va.z));
        lo.z = bf2pack(vb.y - trunc_hi(vb.y), vb.x - trunc_hi(vb.x));
        lo.w = bf2pack(vb.w - trunc_hi(vb.w), vb.z - trunc_hi(vb.z));
        const uint32_t so = (uint32_t)(row * 1024 + ((g ^ (row & 7)) << 4));
        *(uint4*)(smem + S_BH + so) = hi;
        *(uint4*)(smem + S_BL + so) = lo;
    }

    for (int i = tid; i < Bq * U; i += 256) {
        const int b = i >> USH, uu = i & (U - 1), u = u0 + uu;
        hArr[0][b * Hq + u] = h0 ? packHL(h0[b * Hq + u]) : 0u;
        cD        [b * Hq + u] = c0 ? c0[b * Hq + u] : 0.f;
    }
    barTgt += G; gbar(slot, barTgt);

    const int rowA = (lane & 15);
    const int agoff = lane >> 4;
    const int bnt   = lane >> 4;
    const int bgoff = (lane >> 3) & 1;

    int ping = 0;
    for (int t = 0; t < T; t++) {
        const int tt = (dir == 1 && revDir1) ? (T - 1 - t) : t;
        const unsigned* hI = hArr[ping];
        unsigned*       hO = hArr[ping ^ 1];

#pragma unroll
        for (int it = 0; it < 16; it++) {
            const int slotI = tid + it * 256;
            const int row = slotI >> 6, g = slotI & 63;
            const uint4* p = (const uint4*)(hI + (size_t)row * Hq + g * 8);
            const uint4 v0 = __ldcg(p);
            const uint4 v1 = __ldcg(p + 1);
            uint4 hi, lo;
            hi.x = prmt(v0.x, v0.y, 0x7632); hi.y = prmt(v0.z, v0.w, 0x7632);
            hi.z = prmt(v1.x, v1.y, 0x7632); hi.w = prmt(v1.z, v1.w, 0x7632);
            lo.x = prmt(v0.x, v0.y, 0x5410); lo.y = prmt(v0.z, v0.w, 0x5410);
            lo.z = prmt(v1.x, v1.y, 0x5410); lo.w = prmt(v1.z, v1.w, 0x5410);
            const uint32_t so = (uint32_t)(row * 1024 + ((g ^ (row & 7)) << 4));
            *(uint4*)(smem + S_AH + so) = hi;
            *(uint4*)(smem + S_AL + so) = lo;
        }
        __syncthreads();

        float acc[WNT][4];
#pragma unroll
        for (int nt = 0; nt < WNT; nt++)
#pragma unroll
            for (int q = 0; q < 4; q++) acc[nt][q] = 0.f;

#pragma unroll 4
        for (int ks = 0; ks < 32; ks++) {
            const int rA = mi * 16 + rowA;
            const uint32_t aoff = (uint32_t)(rA * 1024 + (((ks * 2 + agoff) ^ (rA & 7)) << 4));
            uint32_t ah[4], al[4], bh[2 * WNT], bl[2 * WNT];
            LDM_X4(ah[0], ah[1], ah[2], ah[3], sb + S_AH + aoff);
            LDM_X4(al[0], al[1], al[2], al[3], sb + S_AL + aoff);
            if (WNT == 2) {
                const int rB = nh * 16 + bnt * 8 + (lane & 7);
                const uint32_t boff = (uint32_t)(rB * 1024 + (((ks * 2 + bgoff) ^ (rB & 7)) << 4));
                LDM_X4(bh[0], bh[1], bh[2], bh[3], sb + S_BH + boff);
                LDM_X4(bl[0], bl[1], bl[2], bl[3], sb + S_BL + boff);
            } else {
                const int rB = nh * 8 + (lane & 7);
                const uint32_t boff = (uint32_t)(rB * 1024 + (((ks * 2 + bgoff) ^ (rB & 7)) << 4));
                LDM_X2(bh[0], bh[1], sb + S_BH + boff);
                LDM_X2(bl[0], bl[1], sb + S_BL + boff);
            }
#pragma unroll
            for (int nt = 0; nt < WNT; nt++)
                MMA_BF16(acc[nt][0], acc[nt][1], acc[nt][2], acc[nt][3],
                         ah[0], ah[1], ah[2], ah[3], bh[nt * 2], bh[nt * 2 + 1]);
#pragma unroll
            for (int nt = 0; nt < WNT; nt++)
                MMA_BF16(acc[nt][0], acc[nt][1], acc[nt][2], acc[nt][3],
                         ah[0], ah[1], ah[2], ah[3], bl[nt * 2], bl[nt * 2 + 1]);
#pragma unroll
            for (int nt = 0; nt < WNT; nt++)
                MMA_BF16(acc[nt][0], acc[nt][1], acc[nt][2], acc[nt][3],
                         al[0], al[1], al[2], al[3], bh[nt * 2], bh[nt * 2 + 1]);
        }

        {
            const int gr  = lane >> 2;
            const int gcq = (lane & 3) * 2;
            const int m = mi * 16 + gr;
#pragma unroll
            for (int nt = 0; nt < WNT; nt++) {
                const int gc = nh * (WNT * 8) + nt * 8 + gcq;
                *(float2*)&Gs[m * GSs + gc]       = make_float2(acc[nt][0], acc[nt][1]);
                *(float2*)&Gs[(m + 8) * GSs + gc] = make_float2(acc[nt][2], acc[nt][3]);
            }
        }
        __syncthreads();

#pragma unroll
        for (int i = tid; i < Bq * U; i += 256) {
            const int b = i >> USH, uu = i & (U - 1);
            const int u = u0 + uu;
            const size_t xb = ((size_t)b * T + tt) * Gq + u;
            const float iv = Gs[b * GSs + 0 * U + uu] + xpd[xb];
            const float fv = Gs[b * GSs + 1 * U + uu] + xpd[xb + 512];
            const float gv = Gs[b * GSs + 2 * U + uu] + xpd[xb + 1024];
            const float ov = Gs[b * GSs + 3 * U + uu] + xpd[xb + 1536];
            const float cOld = cD[b * Hq + u];
            const float si = fast_sigmoid(iv);
            const float sf = fast_sigmoid(fv);
            const float so = fast_sigmoid(ov);
            const float cN = sf * cOld + si * fast_tanh(gv);
            const float hN = so * fast_tanh(cN);
            const unsigned w = packHL(hN);
            cD[b * Hq + u] = cN;
            hO[b * Hq + u] = w;
            if (yh) {
                const size_t m = (size_t)b * T + tt;
                const int col = dir * yDirMult + u;
                const size_t yi = tidx(m, col, yKC);
                yh[yi] = (unsigned short)(w >> 16);
                yl[yi] = (unsigned short)(w & 0xFFFFu);
            }
        }

        if (t + 1 < T) { barTgt += G; gbar(slot, barTgt); }
        ping ^= 1;
    }

    if (hFin) {
        for (int i = tid; i < Bq * U; i += 256) {
            const int b = i >> USH, uu = i & (U - 1), u = u0 + uu;
            hFin[b * 1024 + dir * 512 + u] = unpackHL(hArr[ping][b * Hq + u]);
            cFin[b * 1024 + dir * 512 + u] = cD[b * Hq + u];
        }
    }
}

#define SMEM_ENC (128 * 1024 + 2 * 32 * 1024 + 64 * 34 * 4)
#define SMEM_DEC (128 * 1024 + 2 * 16 * 1024 + 64 * 18 * 4)

// decoder input: concat(tgt_in, sc_emb[scenario[b]]) -> tiled planes (K=640)
__global__ void build_dcat(const float* __restrict__ tgt, const float* __restrict__ scEmb,
                           const int* __restrict__ scen,
                           unsigned short* __restrict__ oh, unsigned short* __restrict__ ol)
{
    const size_t i = (size_t)blockIdx.x * 256 + threadIdx.x;
    if (i >= (size_t)Bq * TDq * 640) return;
    const size_t r = i / 640;
    const int j = (int)(i - r * 640);
    float v;
    if (j < 128) v = tgt[r * 128 + j];
    else         v = scEmb[scen[r / TDq] * 512 + (j - 128)];
    const unsigned w = packHL(v);
    const size_t o = tidx(r, j, 20);
    oh[o] = (unsigned short)(w >> 16);
    ol[o] = (unsigned short)(w & 0xFFFFu);
}

// ---------------------------------------------------------------------------
extern "C" void kernel_launch(void* const* d_in, const int* in_sizes, int n_in,
                              void* d_out, int out_size)
{
    (void)in_sizes; (void)n_in; (void)out_size;
    const float* src   = (const float*)d_in[0];
    const float* tgt   = (const float*)d_in[1];
    const int*   scen  = (const int*)  d_in[2];
    const float* eWih0 = (const float*)d_in[3];
    const float* eWhh0 = (const float*)d_in[4];
    const float* eB0   = (const float*)d_in[5];
    const float* eWih  = (const float*)d_in[6];
    const float* eWhh  = (const float*)d_in[7];
    const float* eB    = (const float*)d_in[8];
    const float* hbW   = (const float*)d_in[9];
    const float* hbB   = (const float*)d_in[10];
    const float* cbW   = (const float*)d_in[11];
    const float* cbB   = (const float*)d_in[12];
    const float* scEmb = (const float*)d_in[13];
    const float* dWih0 = (const float*)d_in[14];
    const float* dWhh0 = (const float*)d_in[15];
    const float* dB0   = (const float*)d_in[16];
    const float* dWih  = (const float*)d_in[17];
    const float* dWhh  = (const float*)d_in[18];
    const float* dB    = (const float*)d_in[19];
    const float* outW  = (const float*)d_in[20];
    const float* outB  = (const float*)d_in[21];
    float* out = (float*)d_out;

    float *xp, *cst, *hsP, *csP, *h0P, *c0P;
    unsigned *hwork, *barP;
    unsigned short *Ah, *Al, *Wh, *Wl;
    cudaGetSymbolAddress((void**)&xp,    g_xp);
    cudaGetSymbolAddress((void**)&hwork, g_hwork);
    cudaGetSymbolAddress((void**)&cst,   g_cwork);
    cudaGetSymbolAddress((void**)&hsP,   g_hs);
    cudaGetSymbolAddress((void**)&csP,   g_cs);
    cudaGetSymbolAddress((void**)&h0P,   g_h0);
    cudaGetSymbolAddress((void**)&c0P,   g_c0);
    cudaGetSymbolAddress((void**)&barP,  g_barSlots);
    cudaGetSymbolAddress((void**)&Ah,    g_Ah);
    cudaGetSymbolAddress((void**)&Al,    g_Al);
    cudaGetSymbolAddress((void**)&Wh,    g_Wh);
    cudaGetSymbolAddress((void**)&Wl,    g_Wl);
    unsigned* hA = hwork;
    unsigned* hB = hwork + 2 * Bq * Hq;

    cudaFuncSetAttribute(lstm_persist<32>, cudaFuncAttributeMaxDynamicSharedMemorySize, SMEM_ENC);
    cudaFuncSetAttribute(lstm_persist<16>, cudaFuncAttributeMaxDynamicSharedMemorySize, SMEM_DEC);
    cudaFuncSetAttribute(mma_xp, cudaFuncAttributeMaxDynamicSharedMemorySize, TB_SMEM);

    const int ME = Bq * TSq;   // 19200
    const int MD = Bq * TDq;   // 11520

    cudaMemsetAsync(barP, 0, 16 * 32 * sizeof(unsigned), 0);

    // ======================= encoder =======================
    conv_tiled<<<(int)(((size_t)ME * Fq / 4 + 255) / 256), 256>>>(src, Ah, Al, ME, Fq);

    int inDim = Fq;
    for (int l = 0; l < Lq; l++) {
        const float* Wih = l ? eWih + (size_t)(l - 1) * 2 * Gq * 1024 : eWih0;
        const float* bih = l ? eB   + (size_t)(l - 1) * 2 * Gq        : eB0;

        conv_tiled<<<(int)(((size_t)2 * Gq * inDim / 4 + 255) / 256), 256>>>(
            Wih, Wh, Wl, 2 * Gq, inDim);
        const size_t wZt = (size_t)16 * (inDim >> 5) * TILE_E;
        mma_xp<<<dim3(Gq / 128, ME / 128, 2), 256, TB_SMEM>>>(
            Ah, Al, Wh, Wl, bih, xp, ME, Gq, inDim,
            wZt, (size_t)Gq, (size_t)ME * Gq, 0);

        const float* Whh = l ? eWhh + (size_t)(l - 1) * 2 * Gq * Hq : eWhh0;
        const int lastEnc = (l == Lq - 1);
        lstm_persist<32><<<128, 256, SMEM_ENC>>>(
            xp, Whh, nullptr, nullptr, hA, hB, cst,
            lastEnc ? nullptr : Ah, lastEnc ? nullptr : Al,
            hsP + (size_t)l * Bq * 1024, csP + (size_t)l * Bq * 1024,
            TSq, 1, 1024, 512, 2 * l);

        inDim = 1024;
    }

    // ======================= bridges (tanh, tensor cores) =======================
    conv_tiled<<<(int)(((size_t)Lq * Bq * 1024 / 4 + 255) / 256), 256>>>(hsP, Ah, Al, Lq * Bq, 1024);
    conv_tiled<<<(int)(((size_t)Hq * 1024 / 4 + 255) / 256), 256>>>(hbW, Wh, Wl, Hq, 1024);
    mma_xp<<<dim3(Hq / 128, (Lq * Bq) / 128, 1), 256, TB_SMEM>>>(
        Ah, Al, Wh, Wl, hbB, h0P, Lq * Bq, Hq, 1024, 0, 0, 0, 1);
    conv_tiled<<<(int)(((size_t)Lq * Bq * 1024 / 4 + 255) / 256), 256>>>(csP, Ah, Al, Lq * Bq, 1024);
    conv_tiled<<<(int)(((size_t)Hq * 1024 / 4 + 255) / 256), 256>>>(cbW, Wh, Wl, Hq, 1024);
    mma_xp<<<dim3(Hq / 128, (Lq * Bq) / 128, 1), 256, TB_SMEM>>>(
        Ah, Al, Wh, Wl, cbB, c0P, Lq * Bq, Hq, 1024, 0, 0, 0, 1);

    // ======================= decoder =======================
    build_dcat<<<(int)(((size_t)Bq * TDq * 640 + 255) / 256), 256>>>(tgt, scEmb, scen, Ah, Al);

    inDim = Fq + Hq;   // 640
    for (int l = 0; l < Lq; l++) {
        const float* Wih = l ? dWih + (size_t)(l - 1) * Gq * Hq : dWih0;
        const float* bih = l ? dB   + (size_t)(l - 1) * Gq      : dB0;

        conv_tiled<<<(int)(((size_t)Gq * inDim / 4 + 255) / 256), 256>>>(
            Wih, Wh, Wl, Gq, inDim);
        mma_xp<<<dim3(Gq / 128, MD / 128, 1), 256, TB_SMEM>>>(
            Ah, Al, Wh, Wl, bih, xp, MD, Gq, inDim, 0, 0, 0, 0);

        const float* Whh = l ? dWhh + (size_t)(l - 1) * Gq * Hq : dWhh0;
        lstm_persist<16><<<128, 256, SMEM_DEC>>>(
            xp, Whh, h0P + (size_t)l * Bq * Hq, c0P + (size_t)l * Bq * Hq,
            hA, hB, cst, Ah, Al, nullptr, nullptr,
            TDq, 0, 512, 0, 8 + l);

        inDim = Hq;
    }

    // output projection straight into d_out
    conv_tiled<<<(int)(((size_t)Fq * Hq / 4 + 255) / 256), 256>>>(outW, Wh, Wl, Fq, Hq);
    mma_xp<<<dim3(Fq / 128, MD / 128, 1), 256, TB_SMEM>>>(
        Ah, Al, Wh, Wl, outB, out, MD, Fq, Hq, 0, 0, 0, 0);
}

// round 16
// speedup vs baseline: 1.3079x; 1.1713x over previous
#include <cuda_runtime.h>
#include <cuda_bf16.h>
#include <math.h>
#include <stdint.h>

#define Bq 64
#define TSq 300
#define TDq 180
#define Fq 128
#define Hq 512
#define Lq 4
#define Gq 2048   // 4*H
#define TILE_E 5120          // 128 rows x 40 u16 per (tile, kChunk)

// ---------------- static device scratch (no runtime allocation) ----------------
__device__ float g_xp[(size_t)2 * Bq * TSq * Gq];
__device__ unsigned g_hwork[2][2 * Bq * Hq];          // packed bf16 hi|lo h state
__device__ float g_cwork[2 * Bq * Hq];
__device__ float g_hs[Lq * Bq * 1024];
__device__ float g_cs[Lq * Bq * 1024];
__device__ float g_h0[Lq * Bq * Hq];
__device__ float g_c0[Lq * Bq * Hq];
__device__ unsigned g_barSlots[32 * 32];
// tiled-padded bf16 operand planes: [tile128][kc32][128][40]
__device__ unsigned short g_Ah[(size_t)150 * 32 * TILE_E];
__device__ unsigned short g_Al[(size_t)150 * 32 * TILE_E];
__device__ unsigned short g_Wh[(size_t)2 * 16 * 32 * TILE_E];
__device__ unsigned short g_Wl[(size_t)2 * 16 * 32 * TILE_E];

// -------- helpers (compute_103-safe) -----
__device__ __forceinline__ uint32_t smem_u32(const void* p) {
    uint32_t a;
    asm("{ .reg .u64 t; cvta.to.shared.u64 t, %1; cvt.u32.u64 %0, t; }" : "=r"(a) : "l"(p));
    return a;
}
#define LDM_X4(r0, r1, r2, r3, addr) \
    asm volatile("ldmatrix.sync.aligned.m8n8.x4.shared.b16 {%0,%1,%2,%3}, [%4];" \
        : "=r"(r0), "=r"(r1), "=r"(r2), "=r"(r3) : "r"(addr))
#define LDM_X2(r0, r1, addr) \
    asm volatile("ldmatrix.sync.aligned.m8n8.x2.shared.b16 {%0,%1}, [%2];" \
        : "=r"(r0), "=r"(r1) : "r"(addr))
#define MMA_BF16(c0, c1, c2, c3, a0, a1, a2, a3, b0, b1) \
    asm volatile("mma.sync.aligned.m16n8k16.row.col.f32.bf16.bf16.f32 " \
        "{%0,%1,%2,%3}, {%4,%5,%6,%7}, {%8,%9}, {%0,%1,%2,%3};" \
        : "+f"(c0), "+f"(c1), "+f"(c2), "+f"(c3) \
        : "r"(a0), "r"(a1), "r"(a2), "r"(a3), "r"(b0), "r"(b1))

// mbarrier + bulk-async
#define MB_INIT(mb, cnt) \
    asm volatile("mbarrier.init.shared.b64 [%0], %1;" :: "r"(mb), "r"(cnt) : "memory")
#define MB_EXPECT(mb, bytes) \
    asm volatile("mbarrier.arrive.expect_tx.shared.b64 _, [%0], %1;" :: "r"(mb), "r"(bytes) : "memory")
#define MB_WAIT(mb, par) do { \
    uint32_t _mb = (mb), _p = (par), _d; \
    asm volatile("{\n\t.reg .pred p;\n\t" \
        "mbarrier.try_wait.parity.acquire.cta.shared::cta.b64 p, [%1], %2;\n\t" \
        "selp.b32 %0, 1, 0, p;\n\t}" : "=r"(_d) : "r"(_mb), "r"(_p) : "memory"); \
    if (!_d) { \
        asm volatile("{\n\t.reg .pred P1;\n\t" \
            "WL_%=:\n\t" \
            "mbarrier.try_wait.parity.acquire.cta.shared::cta.b64 P1, [%0], %1, 0x989680;\n\t" \
            "@P1 bra.uni WD_%=;\n\t" \
            "bra.uni WL_%=;\n\t" \
            "WD_%=:\n\t}" :: "r"(_mb), "r"(_p) : "memory"); \
    } \
} while (0)
#define BULK_G2S(dst, src, nbytes, mb) \
    asm volatile("cp.async.bulk.shared::cta.global.mbarrier::complete_tx::bytes [%0], [%1], %2, [%3];" \
        :: "r"(dst), "l"(src), "r"(nbytes), "r"(mb) : "memory")

__device__ __forceinline__ uint32_t bf2pack(float fhi, float flo) {
    uint32_t r;
    asm("cvt.rn.bf16x2.f32 %0, %1, %2;" : "=r"(r) : "f"(fhi), "f"(flo));
    return r;
}
__device__ __forceinline__ float trunc_hi(float f) {
    return __uint_as_float(__float_as_uint(f) & 0xFFFF0000u);
}
__device__ __forceinline__ unsigned packHL(float f) {
    const float lo = f - trunc_hi(f);
    unsigned lo16;
    asm("{ .reg .b16 t; cvt.rn.bf16.f32 t, %1; cvt.u32.u16 %0, t; }" : "=r"(lo16) : "f"(lo));
    return (__float_as_uint(f) & 0xFFFF0000u) | lo16;
}
__device__ __forceinline__ float unpackHL(unsigned w) {
    return __uint_as_float(w & 0xFFFF0000u) + __uint_as_float(w << 16);
}
__device__ __forceinline__ unsigned prmt(unsigned a, unsigned b, unsigned sel) {
    return __byte_perm(a, b, sel);
}
__device__ __forceinline__ float fast_tanh(float x) {
    float r;
    asm("tanh.approx.f32 %0, %1;" : "=f"(r) : "f"(x));
    return r;
}
__device__ __forceinline__ float fast_sigmoid(float x) {
    return fmaf(0.5f, fast_tanh(0.5f * x), 0.5f);
}
// tiled index: plane[(m>>7)*KC + (k>>5)][m&127][k&31], KC = K/32
__device__ __forceinline__ size_t tidx(size_t m, int k, int KC) {
    return ((m >> 7) * (size_t)KC + (size_t)(k >> 5)) * TILE_E
         + (m & 127) * 40 + (k & 31);
}

// ---------------------------------------------------------------------------
// grid barrier on a monotonic counter
// ---------------------------------------------------------------------------
__device__ __forceinline__ void gbar(unsigned* slot, unsigned tgt)
{
    __syncthreads();
    if (threadIdx.x == 0) {
        asm volatile("red.release.gpu.global.add.u32 [%0], 1;" :: "l"(slot) : "memory");
        unsigned v;
        while (true) {
            asm volatile("ld.acquire.gpu.global.u32 %0, [%1];" : "=r"(v) : "l"(slot) : "memory");
            if (v >= tgt) break;
            __nanosleep(32);
        }
    }
    __syncthreads();
}

// ---------------------------------------------------------------------------
// fp32 row-major [M x K] -> tiled-padded bf16 hi/lo planes. M%128==0, K%32==0.
// ---------------------------------------------------------------------------
__global__ void conv_tiled(const float* __restrict__ in,
                           unsigned short* __restrict__ hi, unsigned short* __restrict__ lo,
                           int M, int K)
{
    const size_t i = ((size_t)blockIdx.x * 256 + threadIdx.x) * 4;
    if (i >= (size_t)M * K) return;
    const size_t m = i / (size_t)K;
    const int k = (int)(i - m * (size_t)K);
    const float4 v = *(const float4*)(in + i);
    uint2 h, l;
    h.x = prmt(__float_as_uint(v.x), __float_as_uint(v.y), 0x7632);
    h.y = prmt(__float_as_uint(v.z), __float_as_uint(v.w), 0x7632);
    l.x = bf2pack(v.y - trunc_hi(v.y), v.x - trunc_hi(v.x));
    l.y = bf2pack(v.w - trunc_hi(v.w), v.z - trunc_hi(v.z));
    const size_t o = tidx(m, k, K >> 5);
    *(uint2*)(hi + o) = h;
    *(uint2*)(lo + o) = l;
}

// ---------------------------------------------------------------------------
// Tiled bulk-async split-bf16 GEMM (round-15, best measured)
// ---------------------------------------------------------------------------
#define TB_PLANE  10240
#define TB_STAGE  (4 * TB_PLANE)
#define TB_SMEM   (2 * TB_STAGE + 64)

__global__ __launch_bounds__(256, 2)
void mma_xp(const unsigned short* __restrict__ Ah, const unsigned short* __restrict__ Al,
            const unsigned short* __restrict__ Wh, const unsigned short* __restrict__ Wl,
            const float* __restrict__ bias, float* __restrict__ C,
            int M, int N, int K, size_t wZt, size_t bZ, size_t cZ, int act)
{
    extern __shared__ __align__(128) char smem[];
    const uint32_t sbase  = smem_u32(smem);
    const uint32_t mbBase = sbase + 2 * TB_STAGE;

    Wh   += blockIdx.z * wZt;
    Wl   += blockIdx.z * wZt;
    bias += blockIdx.z * bZ;
    C    += blockIdx.z * cZ;
    const int n0 = blockIdx.x * 128;
    const int m0 = blockIdx.y * 128;
    const int KC = K >> 5;

    const int tid  = threadIdx.x;
    const int lane = tid & 31;
    const int warp = tid >> 5;
    const int wm = warp >> 2;
    const int wn = warp & 3;

    const unsigned short* aTh = Ah + (size_t)blockIdx.y * KC * TILE_E;
    const unsigned short* aTl = Al + (size_t)blockIdx.y * KC * TILE_E;
    const unsigned short* wTh = Wh + (size_t)blockIdx.x * KC * TILE_E;
    const unsigned short* wTl = Wl + (size_t)blockIdx.x * KC * TILE_E;

    if (tid < 2) MB_INIT(mbBase + tid * 8, 1);
    __syncthreads();

    float acc[4][4][4];
#pragma unroll
    for (int i = 0; i < 4; i++)
#pragma unroll
        for (int j = 0; j < 4; j++)
#pragma unroll
            for (int q = 0; q < 4; q++) acc[i][j][q] = 0.f;

    const int arow = wm * 64 + (lane & 15);
    const int agoff = lane >> 4;
    const int brow = wn * 32 + (lane & 7);
    const int bgoff = (lane >> 3) & 1;
    const int bnt   = lane >> 4;

    const int nch = KC;

#define TISSUE(c) do { \
    const uint32_t _sb = sbase + (uint32_t)((c) & 1) * TB_STAGE; \
    const uint32_t _mb = mbBase + ((c) & 1) * 8; \
    const size_t _o = (size_t)(c) * TILE_E; \
    MB_EXPECT(_mb, 40960); \
    BULK_G2S(_sb,                aTh + _o, TB_PLANE, _mb); \
    BULK_G2S(_sb + TB_PLANE,     aTl + _o, TB_PLANE, _mb); \
    BULK_G2S(_sb + 2 * TB_PLANE, wTh + _o, TB_PLANE, _mb); \
    BULK_G2S(_sb + 3 * TB_PLANE, wTl + _o, TB_PLANE, _mb); \
} while (0)

    if (tid == 0) { TISSUE(0); TISSUE(1); }

    for (int c = 0; c < nch; c++) {
        MB_WAIT(mbBase + (c & 1) * 8, (c >> 1) & 1);

        const uint32_t buf = sbase + (uint32_t)(c & 1) * TB_STAGE;
        const uint32_t aH = buf;
        const uint32_t aL = buf + TB_PLANE;
        const uint32_t wH = buf + 2 * TB_PLANE;
        const uint32_t wL = buf + 3 * TB_PLANE;

#pragma unroll
        for (int ks = 0; ks < 2; ks++) {
            uint32_t af[4][4], bh[4][2], bl[4][2];
#pragma unroll
            for (int mt = 0; mt < 4; mt++) {
                const int rA = arow + mt * 16;
                const uint32_t ad = aH + (uint32_t)(rA * 80 + ((ks * 2 + agoff) << 4));
                LDM_X4(af[mt][0], af[mt][1], af[mt][2], af[mt][3], ad);
            }
#pragma unroll
            for (int p = 0; p < 2; p++) {
                const int rB = brow + (p * 2 + bnt) * 8;
                const uint32_t off = (uint32_t)(rB * 80 + ((ks * 2 + bgoff) << 4));
                LDM_X4(bh[p * 2][0], bh[p * 2][1], bh[p * 2 + 1][0], bh[p * 2 + 1][1], wH + off);
                LDM_X4(bl[p * 2][0], bl[p * 2][1], bl[p * 2 + 1][0], bl[p * 2 + 1][1], wL + off);
            }
#pragma unroll
            for (int mt = 0; mt < 4; mt++)
#pragma unroll
                for (int nt = 0; nt < 4; nt++)
                    MMA_BF16(acc[mt][nt][0], acc[mt][nt][1], acc[mt][nt][2], acc[mt][nt][3],
                             af[mt][0], af[mt][1], af[mt][2], af[mt][3],
                             bh[nt][0], bh[nt][1]);
#pragma unroll
            for (int mt = 0; mt < 4; mt++)
#pragma unroll
                for (int nt = 0; nt < 4; nt++)
                    MMA_BF16(acc[mt][nt][0], acc[mt][nt][1], acc[mt][nt][2], acc[mt][nt][3],
                             af[mt][0], af[mt][1], af[mt][2], af[mt][3],
                             bl[nt][0], bl[nt][1]);
#pragma unroll
            for (int mt = 0; mt < 4; mt++) {
                const int rA = arow + mt * 16;
                const uint32_t ad = aL + (uint32_t)(rA * 80 + ((ks * 2 + agoff) << 4));
                LDM_X4(af[mt][0], af[mt][1], af[mt][2], af[mt][3], ad);
            }
#pragma unroll
            for (int mt = 0; mt < 4; mt++)
#pragma unroll
                for (int nt = 0; nt < 4; nt++)
                    MMA_BF16(acc[mt][nt][0], acc[mt][nt][1], acc[mt][nt][2], acc[mt][nt][3],
                             af[mt][0], af[mt][1], af[mt][2], af[mt][3],
                             bh[nt][0], bh[nt][1]);
        }

        __syncthreads();
        if (tid == 0 && c + 2 < nch) TISSUE(c + 2);
    }

    const int mE = m0 + wm * 64 + (lane >> 2);
    const int nE = n0 + wn * 32 + (lane & 3) * 2;
#pragma unroll
    for (int mt = 0; mt < 4; mt++) {
#pragma unroll
        for (int nt = 0; nt < 4; nt++) {
            const int m = mE + mt * 16;
            const int n = nE + nt * 8;
            const float b0 = bias[n], b1 = bias[n + 1];
            float v00 = acc[mt][nt][0] + b0, v01 = acc[mt][nt][1] + b1;
            float v10 = acc[mt][nt][2] + b0, v11 = acc[mt][nt][3] + b1;
            if (act) { v00 = tanhf(v00); v01 = tanhf(v01); v10 = tanhf(v10); v11 = tanhf(v11); }
            *(float2*)(C + (size_t)m * N + n)       = make_float2(v00, v01);
            *(float2*)(C + (size_t)(m + 8) * N + n) = make_float2(v10, v11);
        }
    }
}

// ---------------------------------------------------------------------------
// Persistent LSTM layer, BATCH-SPLIT: each block owns 32 batch rows x NGC
// gate cols. Encoder NGC=64 (16 units): 128 blocks = 2dir x 2bh x 32ug.
// Decoder NGC=32 (8 units): 128 blocks = 2bh x 64ug. Barrier group =
// (dir,bh): h broadcast traffic halves vs full-batch blocks.
// smem: A[32x1KB]x2 | W[NGCx1KB]x2 | Gs[32][NGC+2]
// ---------------------------------------------------------------------------
template<int NGC>
__global__ __launch_bounds__(256)
void lstm_persist(const float* __restrict__ xp, const float* __restrict__ Whh,
                  const float* __restrict__ h0, const float* __restrict__ c0,
                  unsigned* __restrict__ hA, unsigned* __restrict__ hB,
                  float* __restrict__ cSt,
                  unsigned short* __restrict__ yh, unsigned short* __restrict__ yl,
                  float* __restrict__ hFin, float* __restrict__ cFin,
                  int T, int revDir1, int yStride, int yDirMult, int slotIdx)
{
    constexpr int U    = NGC / 4;                 // units per block (16 or 8)
    constexpr int USH  = (NGC == 64) ? 4 : 3;
    constexpr int WNT  = NGC / 32;                // n8-tile pairs per warp (2 or 1)
    constexpr int GSs  = NGC + 2;
    constexpr unsigned G = (NGC == 64) ? 32u : 64u;
    constexpr uint32_t S_AH = 0;
    constexpr uint32_t S_AL = 32 * 1024;
    constexpr uint32_t S_BH = 64 * 1024;
    constexpr uint32_t S_BL = S_BH + NGC * 1024;
    constexpr uint32_t S_GS = S_BL + NGC * 1024;

    extern __shared__ __align__(128) char smem[];
    const uint32_t sb = smem_u32(smem);
    float* Gs = (float*)(smem + S_GS);

    const int tid  = threadIdx.x;
    const int lane = tid & 31;
    const int warp = tid >> 5;
    const int mi = warp >> 2;          // 0..1 : m16 tile within 32 batch rows
    const int nq = warp & 3;           // 0..3 : 16-or-8-col quarter

    int dir, bh, u0, grp;
    if (NGC == 64) {
        dir = blockIdx.x >> 6; bh = (blockIdx.x >> 5) & 1;
        u0 = (blockIdx.x & 31) * 16; grp = dir * 2 + bh;
    } else {
        dir = 0; bh = blockIdx.x >> 6;
        u0 = (blockIdx.x & 63) * 8; grp = bh;
    }
    const int bOff = bh * 32;

    unsigned* slot = g_barSlots + (size_t)(slotIdx + grp) * 32;
    unsigned barTgt = 0;

    const float* xpd = xp  + (size_t)dir * Bq * T * Gq;
    const float* Wd  = Whh + (size_t)dir * Gq * Hq;
    unsigned* hArr[2] = { hA + dir * Bq * Hq, hB + dir * Bq * Hq };
    float* cD = cSt + dir * Bq * Hq;
    const int yKC = yStride >> 5;

    // ---- convert Whh rows (gate-gathered) into smem bf16 hi/lo, swizzled ----
    for (int i = tid; i < NGC * 64; i += 256) {
        const int row = i >> 6;
        const int g   = i & 63;
        const int gate = row / U;
        const int uu   = row & (U - 1);
        const int wrow = (gate << 9) + u0 + uu;
        const float4 va = *(const float4*)(Wd + (size_t)wrow * Hq + g * 8);
        const float4 vb = *(const float4*)(Wd + (size_t)wrow * Hq + g * 8 + 4);
        uint4 hi, lo;
        hi.x = prmt(__float_as_uint(va.x), __float_as_uint(va.y), 0x7632);
        hi.y = prmt(__float_as_uint(va.z), __float_as_uint(va.w), 0x7632);
        hi.z = prmt(__float_as_uint(vb.x), __float_as_uint(vb.y), 0x7632);
        hi.w = prmt(__float_as_uint(vb.z), __float_as_uint(vb.w), 0x7632);
        lo.x = bf2pack(va.y - trunc_hi(va.y), va.x - trunc_hi(va.x));
        lo.y = bf2pack(va.w - trunc_hi(va.w), va.z - trunc_hi(va.z));
        lo.z = bf2pack(vb.y - trunc_hi(vb.y), vb.x - trunc_hi(vb.x));
        lo.w = bf2pack(vb.w - trunc_hi(vb.w), vb.z - trunc_hi(vb.z));
        const uint32_t so = (uint32_t)(row * 1024 + ((g ^ (row & 7)) << 4));
        *(uint4*)(smem + S_BH + so) = hi;
        *(uint4*)(smem + S_BL + so) = lo;
    }

    // ---- init h (packed), c for owned (32 batch x U unit) slice ----
    for (int i = tid; i < 32 * U; i += 256) {
        const int b = bOff + (i >> USH), uu = i & (U - 1), u = u0 + uu;
        hArr[0][b * Hq + u] = h0 ? packHL(h0[b * Hq + u]) : 0u;
        cD        [b * Hq + u] = c0 ? c0[b * Hq + u] : 0.f;
    }
    barTgt += G; gbar(slot, barTgt);

    const int rowA = (lane & 15);
    const int agoff = lane >> 4;
    const int bnt   = lane >> 4;
    const int bgoff = (lane >> 3) & 1;

    int ping = 0;
    for (int t = 0; t < T; t++) {
        const int tt = (dir == 1 && revDir1) ? (T - 1 - t) : t;
        const unsigned* hI = hArr[ping];
        unsigned*       hO = hArr[ping ^ 1];

        // ---- stage 32 rows of packed h -> smem hi/lo (PRMT only) ----
#pragma unroll
        for (int it = 0; it < 8; it++) {
            const int slotI = tid + it * 256;
            const int row = slotI >> 6, g = slotI & 63;
            const uint4* p = (const uint4*)(hI + (size_t)(bOff + row) * Hq + g * 8);
            const uint4 v0 = __ldcg(p);
            const uint4 v1 = __ldcg(p + 1);
            uint4 hi, lo;
            hi.x = prmt(v0.x, v0.y, 0x7632); hi.y = prmt(v0.z, v0.w, 0x7632);
            hi.z = prmt(v1.x, v1.y, 0x7632); hi.w = prmt(v1.z, v1.w, 0x7632);
            lo.x = prmt(v0.x, v0.y, 0x5410); lo.y = prmt(v0.z, v0.w, 0x5410);
            lo.z = prmt(v1.x, v1.y, 0x5410); lo.w = prmt(v1.z, v1.w, 0x5410);
            const uint32_t so = (uint32_t)(row * 1024 + ((g ^ (row & 7)) << 4));
            *(uint4*)(smem + S_AH + so) = hi;
            *(uint4*)(smem + S_AL + so) = lo;
        }
        __syncthreads();

        float acc[WNT][4];
#pragma unroll
        for (int nt = 0; nt < WNT; nt++)
#pragma unroll
            for (int q = 0; q < 4; q++) acc[nt][q] = 0.f;

#pragma unroll 4
        for (int ks = 0; ks < 32; ks++) {
            const int rA = mi * 16 + rowA;
            const uint32_t aoff = (uint32_t)(rA * 1024 + (((ks * 2 + agoff) ^ (rA & 7)) << 4));
            uint32_t ah[4], al[4], bhf[2 * WNT], blf[2 * WNT];
            LDM_X4(ah[0], ah[1], ah[2], ah[3], sb + S_AH + aoff);
            LDM_X4(al[0], al[1], al[2], al[3], sb + S_AL + aoff);
            if (WNT == 2) {
                const int rB = nq * 16 + bnt * 8 + (lane & 7);
                const uint32_t boff = (uint32_t)(rB * 1024 + (((ks * 2 + bgoff) ^ (rB & 7)) << 4));
                LDM_X4(bhf[0], bhf[1], bhf[2], bhf[3], sb + S_BH + boff);
                LDM_X4(blf[0], blf[1], blf[2], blf[3], sb + S_BL + boff);
            } else {
                const int rB = nq * 8 + (lane & 7);
                const uint32_t boff = (uint32_t)(rB * 1024 + (((ks * 2 + bgoff) ^ (rB & 7)) << 4));
                LDM_X2(bhf[0], bhf[1], sb + S_BH + boff);
                LDM_X2(blf[0], blf[1], sb + S_BL + boff);
            }
#pragma unroll
            for (int nt = 0; nt < WNT; nt++)
                MMA_BF16(acc[nt][0], acc[nt][1], acc[nt][2], acc[nt][3],
                         ah[0], ah[1], ah[2], ah[3], bhf[nt * 2], bhf[nt * 2 + 1]);
#pragma unroll
            for (int nt = 0; nt < WNT; nt++)
                MMA_BF16(acc[nt][0], acc[nt][1], acc[nt][2], acc[nt][3],
                         ah[0], ah[1], ah[2], ah[3], blf[nt * 2], blf[nt * 2 + 1]);
#pragma unroll
            for (int nt = 0; nt < WNT; nt++)
                MMA_BF16(acc[nt][0], acc[nt][1], acc[nt][2], acc[nt][3],
                         al[0], al[1], al[2], al[3], bhf[nt * 2], bhf[nt * 2 + 1]);
        }

        {
            const int gr  = lane >> 2;
            const int gcq = (lane & 3) * 2;
            const int m = mi * 16 + gr;
#pragma unroll
            for (int nt = 0; nt < WNT; nt++) {
                const int gc = nq * (WNT * 8) + nt * 8 + gcq;
                *(float2*)&Gs[m * GSs + gc]       = make_float2(acc[nt][0], acc[nt][1]);
                *(float2*)&Gs[(m + 8) * GSs + gc] = make_float2(acc[nt][2], acc[nt][3]);
            }
        }
        __syncthreads();

        // ---- cell update for 32 batch x U units ----
#pragma unroll
        for (int i = tid; i < 32 * U; i += 256) {
            const int bl = i >> USH, uu = i & (U - 1);
            const int b = bOff + bl, u = u0 + uu;
            const size_t xb = ((size_t)b * T + tt) * Gq + u;
            const float iv = Gs[bl * GSs + 0 * U + uu] + xpd[xb];
            const float fv = Gs[bl * GSs + 1 * U + uu] + xpd[xb + 512];
            const float gv = Gs[bl * GSs + 2 * U + uu] + xpd[xb + 1024];
            const float ov = Gs[bl * GSs + 3 * U + uu] + xpd[xb + 1536];
            const float cOld = cD[b * Hq + u];
            const float si = fast_sigmoid(iv);
            const float sf = fast_sigmoid(fv);
            const float so = fast_sigmoid(ov);
            const float cN = sf * cOld + si * fast_tanh(gv);
            const float hN = so * fast_tanh(cN);
            const unsigned w = packHL(hN);
            cD[b * Hq + u] = cN;
            hO[b * Hq + u] = w;
            if (yh) {
                const size_t m = (size_t)b * T + tt;
                const int col = dir * yDirMult + u;
                const size_t yi = tidx(m, col, yKC);
                yh[yi] = (unsigned short)(w >> 16);
                yl[yi] = (unsigned short)(w & 0xFFFFu);
            }
        }

        if (t + 1 < T) { barTgt += G; gbar(slot, barTgt); }
        ping ^= 1;
    }

    if (hFin) {
        for (int i = tid; i < 32 * U; i += 256) {
            const int b = bOff + (i >> USH), uu = i & (U - 1), u = u0 + uu;
            hFin[b * 1024 + dir * 512 + u] = unpackHL(hArr[ping][b * Hq + u]);
            cFin[b * 1024 + dir * 512 + u] = cD[b * Hq + u];
        }
    }
}

#define SMEM_ENC (64 * 1024 + 2 * 64 * 1024 + 32 * 66 * 4)
#define SMEM_DEC (64 * 1024 + 2 * 32 * 1024 + 32 * 34 * 4)

// decoder input: concat(tgt_in, sc_emb[scenario[b]]) -> tiled planes (K=640)
__global__ void build_dcat(const float* __restrict__ tgt, const float* __restrict__ scEmb,
                           const int* __restrict__ scen,
                           unsigned short* __restrict__ oh, unsigned short* __restrict__ ol)
{
    const size_t i = (size_t)blockIdx.x * 256 + threadIdx.x;
    if (i >= (size_t)Bq * TDq * 640) return;
    const size_t r = i / 640;
    const int j = (int)(i - r * 640);
    float v;
    if (j < 128) v = tgt[r * 128 + j];
    else         v = scEmb[scen[r / TDq] * 512 + (j - 128)];
    const unsigned w = packHL(v);
    const size_t o = tidx(r, j, 20);
    oh[o] = (unsigned short)(w >> 16);
    ol[o] = (unsigned short)(w & 0xFFFFu);
}

// ---------------------------------------------------------------------------
extern "C" void kernel_launch(void* const* d_in, const int* in_sizes, int n_in,
                              void* d_out, int out_size)
{
    (void)in_sizes; (void)n_in; (void)out_size;
    const float* src   = (const float*)d_in[0];
    const float* tgt   = (const float*)d_in[1];
    const int*   scen  = (const int*)  d_in[2];
    const float* eWih0 = (const float*)d_in[3];
    const float* eWhh0 = (const float*)d_in[4];
    const float* eB0   = (const float*)d_in[5];
    const float* eWih  = (const float*)d_in[6];
    const float* eWhh  = (const float*)d_in[7];
    const float* eB    = (const float*)d_in[8];
    const float* hbW   = (const float*)d_in[9];
    const float* hbB   = (const float*)d_in[10];
    const float* cbW   = (const float*)d_in[11];
    const float* cbB   = (const float*)d_in[12];
    const float* scEmb = (const float*)d_in[13];
    const float* dWih0 = (const float*)d_in[14];
    const float* dWhh0 = (const float*)d_in[15];
    const float* dB0   = (const float*)d_in[16];
    const float* dWih  = (const float*)d_in[17];
    const float* dWhh  = (const float*)d_in[18];
    const float* dB    = (const float*)d_in[19];
    const float* outW  = (const float*)d_in[20];
    const float* outB  = (const float*)d_in[21];
    float* out = (float*)d_out;

    float *xp, *cst, *hsP, *csP, *h0P, *c0P;
    unsigned *hwork, *barP;
    unsigned short *Ah, *Al, *Wh, *Wl;
    cudaGetSymbolAddress((void**)&xp,    g_xp);
    cudaGetSymbolAddress((void**)&hwork, g_hwork);
    cudaGetSymbolAddress((void**)&cst,   g_cwork);
    cudaGetSymbolAddress((void**)&hsP,   g_hs);
    cudaGetSymbolAddress((void**)&csP,   g_cs);
    cudaGetSymbolAddress((void**)&h0P,   g_h0);
    cudaGetSymbolAddress((void**)&c0P,   g_c0);
    cudaGetSymbolAddress((void**)&barP,  g_barSlots);
    cudaGetSymbolAddress((void**)&Ah,    g_Ah);
    cudaGetSymbolAddress((void**)&Al,    g_Al);
    cudaGetSymbolAddress((void**)&Wh,    g_Wh);
    cudaGetSymbolAddress((void**)&Wl,    g_Wl);
    unsigned* hA = hwork;
    unsigned* hB = hwork + 2 * Bq * Hq;

    cudaFuncSetAttribute(lstm_persist<64>, cudaFuncAttributeMaxDynamicSharedMemorySize, SMEM_ENC);
    cudaFuncSetAttribute(lstm_persist<32>, cudaFuncAttributeMaxDynamicSharedMemorySize, SMEM_DEC);
    cudaFuncSetAttribute(mma_xp, cudaFuncAttributeMaxDynamicSharedMemorySize, TB_SMEM);

    const int ME = Bq * TSq;   // 19200
    const int MD = Bq * TDq;   // 11520

    cudaMemsetAsync(barP, 0, 32 * 32 * sizeof(unsigned), 0);

    // ======================= encoder =======================
    conv_tiled<<<(int)(((size_t)ME * Fq / 4 + 255) / 256), 256>>>(src, Ah, Al, ME, Fq);

    int inDim = Fq;
    for (int l = 0; l < Lq; l++) {
        const float* Wih = l ? eWih + (size_t)(l - 1) * 2 * Gq * 1024 : eWih0;
        const float* bih = l ? eB   + (size_t)(l - 1) * 2 * Gq        : eB0;

        conv_tiled<<<(int)(((size_t)2 * Gq * inDim / 4 + 255) / 256), 256>>>(
            Wih, Wh, Wl, 2 * Gq, inDim);
        const size_t wZt = (size_t)16 * (inDim >> 5) * TILE_E;
        mma_xp<<<dim3(Gq / 128, ME / 128, 2), 256, TB_SMEM>>>(
            Ah, Al, Wh, Wl, bih, xp, ME, Gq, inDim,
            wZt, (size_t)Gq, (size_t)ME * Gq, 0);

        const float* Whh = l ? eWhh + (size_t)(l - 1) * 2 * Gq * Hq : eWhh0;
        const int lastEnc = (l == Lq - 1);
        lstm_persist<64><<<128, 256, SMEM_ENC>>>(
            xp, Whh, nullptr, nullptr, hA, hB, cst,
            lastEnc ? nullptr : Ah, lastEnc ? nullptr : Al,
            hsP + (size_t)l * Bq * 1024, csP + (size_t)l * Bq * 1024,
            TSq, 1, 1024, 512, 4 * l);

        inDim = 1024;
    }

    // ======================= bridges (tanh, tensor cores) =======================
    conv_tiled<<<(int)(((size_t)Lq * Bq * 1024 / 4 + 255) / 256), 256>>>(hsP, Ah, Al, Lq * Bq, 1024);
    conv_tiled<<<(int)(((size_t)Hq * 1024 / 4 + 255) / 256), 256>>>(hbW, Wh, Wl, Hq, 1024);
    mma_xp<<<dim3(Hq / 128, (Lq * Bq) / 128, 1), 256, TB_SMEM>>>(
        Ah, Al, Wh, Wl, hbB, h0P, Lq * Bq, Hq, 1024, 0, 0, 0, 1);
    conv_tiled<<<(int)(((size_t)Lq * Bq * 1024 / 4 + 255) / 256), 256>>>(csP, Ah, Al, Lq * Bq, 1024);
    conv_tiled<<<(int)(((size_t)Hq * 1024 / 4 + 255) / 256), 256>>>(cbW, Wh, Wl, Hq, 1024);
    mma_xp<<<dim3(Hq / 128, (Lq * Bq) / 128, 1), 256, TB_SMEM>>>(
        Ah, Al, Wh, Wl, cbB, c0P, Lq * Bq, Hq, 1024, 0, 0, 0, 1);

    // ======================= decoder =======================
    build_dcat<<<(int)(((size_t)Bq * TDq * 640 + 255) / 256), 256>>>(tgt, scEmb, scen, Ah, Al);

    inDim = Fq + Hq;   // 640
    for (int l = 0; l < Lq; l++) {
        const float* Wih = l ? dWih + (size_t)(l - 1) * Gq * Hq : dWih0;
        const float* bih = l ? dB   + (size_t)(l - 1) * Gq      : dB0;

        conv_tiled<<<(int)(((size_t)Gq * inDim / 4 + 255) / 256), 256>>>(
            Wih, Wh, Wl, Gq, inDim);
        mma_xp<<<dim3(Gq / 128, MD / 128, 1), 256, TB_SMEM>>>(
            Ah, Al, Wh, Wl, bih, xp, MD, Gq, inDim, 0, 0, 0, 0);

        const float* Whh = l ? dWhh + (size_t)(l - 1) * Gq * Hq : dWhh0;
        lstm_persist<32><<<128, 256, SMEM_DEC>>>(
            xp, Whh, h0P + (size_t)l * Bq * Hq, c0P + (size_t)l * Bq * Hq,
            hA, hB, cst, Ah, Al, nullptr, nullptr,
            TDq, 0, 512, 0, 16 + 2 * l);

        inDim = Hq;
    }

    // output projection straight into d_out
    conv_tiled<<<(int)(((size_t)Fq * Hq / 4 + 255) / 256), 256>>>(outW, Wh, Wl, Fq, Hq);
    mma_xp<<<dim3(Fq / 128, MD / 128, 1), 256, TB_SMEM>>>(
        Ah, Al, Wh, Wl, outB, out, MD, Fq, Hq, 0, 0, 0, 0);
}